// round 7
// baseline (speedup 1.0000x reference)
#include <cuda_runtime.h>
#include <math.h>
#include <stdint.h>

#define BB   8
#define NB   16          // both graphs merged into one batch
#define NPT  1024
#define KNN  20
#define NROW (NB*NPT)    // 16384

// ------------------------------------------------------------------ packed fp32x2 helpers
__device__ __forceinline__ void ffma2(unsigned long long& d, unsigned long long a, unsigned long long b) {
    asm("fma.rn.f32x2 %0, %1, %2, %0;" : "+l"(d) : "l"(a), "l"(b));
}
__device__ __forceinline__ unsigned long long dup2(float x) {
    unsigned long long r;
    asm("mov.b64 %0, {%1, %1};" : "=l"(r) : "f"(x));
    return r;
}
__device__ __forceinline__ float2 unpk2(unsigned long long v) {
    float2 r;
    asm("mov.b64 {%0, %1}, %2;" : "=f"(r.x), "=f"(r.y) : "l"(v));
    return r;
}
__device__ __forceinline__ unsigned mapkey(float v) {
    unsigned u = __float_as_uint(v);
    return (u & 0x80000000u) ? ~u : (u | 0x80000000u);   // order-preserving; real keys > 0
}

// ------------------------------------------------------------------ scratch
__device__ int   g_idx[NROW*KNN];
__device__ float g_xx [NROW];
__device__ float g_x0 [NROW*4];
__device__ float g_s0 [NROW*128];
__device__ float g_h1 [NROW*64];
__device__ float g_h2 [NROW*64];
__device__ float g_h3 [NROW*128];
__device__ float g_emb[NROW*128];
__device__ float g_part[NB*8*128];
__device__ float g_gc  [NB*128];
__device__ float g_e   [NB*128];

// ------------------------------------------------------------------ transpose both inputs (B,C,N) -> point-major
__global__ void transpose_kernel(const float* __restrict__ f1, const float* __restrict__ f2,
                                 float* __restrict__ x0, float* __restrict__ s0) {
    int j = blockIdx.x * blockDim.x + threadIdx.x;
    int total = NB * 131 * NPT;
    if (j >= total) return;
    int n = j % NPT;
    int c = (j / NPT) % 131;
    int b = j / (131 * NPT);
    const float* in = (b < BB) ? f1 : f2;
    float v = in[((long)(b & 7) * 131 + c) * NPT + n];
    if (c < 3) {
        x0[(b*NPT + n)*4 + c] = v;
        if (c == 0) x0[(b*NPT + n)*4 + 3] = 0.0f;
    } else {
        s0[((long)(b*NPT) + n)*128 + (c - 3)] = v;
    }
}

// ------------------------------------------------------------------ per-point squared norm
template <int CROW>
__global__ void xx_kernel(const float* __restrict__ X, float* __restrict__ xx) {
    int j = blockIdx.x * 256 + threadIdx.x;
    if (j >= NROW) return;
    const float* r = X + (long)j * CROW;
    float a = 0.f;
    #pragma unroll
    for (int c = 0; c < CROW; c++) a += r[c] * r[c];
    xx[j] = a;
}

// ------------------------------------------------------------------ fused KNN: distances computed into registers + REDUX top-20
// block = 512 threads = 16 warps = 16 rows; col tiles of 256 in smem (transposed [c][col])
// lane's 32 keys: j = 8*tile + 4*half + q  ->  local col = 256*tile + 128*half + lane*4 + q
__device__ __forceinline__ unsigned gi_of(int j, int lane) {
    return ((unsigned)(j >> 3) << 8) + (((unsigned)(j >> 2) & 1u) << 7) + (unsigned)(lane * 4) + (unsigned)(j & 3);
}

template <int CROW>
__global__ __launch_bounds__(512) void knn_kernel(const float* __restrict__ X,
                                                  const float* __restrict__ xx,
                                                  int* __restrict__ idxout) {
    extern __shared__ float sm[];
    float* tile = sm;                       // [CROW][256]
    float* srow = tile + CROW * 256;        // [16][CROW]
    float* sxxc = srow + 16 * CROW;         // [256]
    int t = threadIdx.x;
    int warp = t >> 5, lane = t & 31;
    int b  = blockIdx.x / (NPT / 16);
    int r0 = (blockIdx.x % (NPT / 16)) * 16;
    long rowg = (long)(b * NPT) + r0 + warp;

    // load 16 row feature vectors
    for (int i = t; i < 16 * CROW; i += 512)
        srow[i] = X[((long)(b*NPT) + r0 + i / CROW) * CROW + (i % CROW)];
    float xxr = xx[rowg];
    const float* rowf = &srow[warp * CROW];

    unsigned key[32];
    #pragma unroll
    for (int tI = 0; tI < 4; tI++) {
        int c0 = tI * 256;                   // col base of this tile
        __syncthreads();                      // previous tile fully consumed
        // cooperative transposed tile load: 2 threads per column (halves of channels)
        if (CROW == 4) {
            if ((t & 1) == 0) {
                int col = t >> 1;
                float4 v = *(const float4*)&X[((long)(b*NPT) + c0 + col) * 4];
                tile[0*256 + col] = v.x; tile[1*256 + col] = v.y;
                tile[2*256 + col] = v.z; tile[3*256 + col] = v.w;
            }
        } else {
            constexpr int CH = (CROW == 4) ? 4 : CROW / 2;
            int col = t >> 1;
            int ch0 = (t & 1) * CH;
            const float* src = &X[((long)(b*NPT) + c0 + col) * CROW + ch0];
            #pragma unroll
            for (int c4 = 0; c4 < CH / 4; c4++) {
                float4 v = *(const float4*)&src[c4 * 4];
                int cc = ch0 + c4 * 4;
                tile[(cc+0)*256 + col] = v.x; tile[(cc+1)*256 + col] = v.y;
                tile[(cc+2)*256 + col] = v.z; tile[(cc+3)*256 + col] = v.w;
            }
        }
        if (t < 256) sxxc[t] = xx[(long)(b*NPT) + c0 + t];
        __syncthreads();

        unsigned long long acc[4] = {0ull, 0ull, 0ull, 0ull};
        for (int c4 = 0; c4 < CROW / 4; c4++) {
            float4 rv4 = *(const float4*)&rowf[4 * c4];
            float rvf[4] = {rv4.x, rv4.y, rv4.z, rv4.w};
            const float* tb = &tile[4 * c4 * 256];
            #pragma unroll
            for (int q = 0; q < 4; q++) {
                unsigned long long rv = dup2(rvf[q]);
                ulonglong2 ca = *(const ulonglong2*)&tb[q*256 + lane*4];
                ulonglong2 cb = *(const ulonglong2*)&tb[q*256 + 128 + lane*4];
                ffma2(acc[0], rv, ca.x); ffma2(acc[1], rv, ca.y);
                ffma2(acc[2], rv, cb.x); ffma2(acc[3], rv, cb.y);
            }
        }
        float2 pa0 = unpk2(acc[0]), pa1 = unpk2(acc[1]);
        float2 pb0 = unpk2(acc[2]), pb1 = unpk2(acc[3]);
        float4 xca = *(const float4*)&sxxc[lane*4];
        float4 xcb = *(const float4*)&sxxc[128 + lane*4];
        key[8*tI+0] = mapkey(2.f*pa0.x - xxr - xca.x);
        key[8*tI+1] = mapkey(2.f*pa0.y - xxr - xca.y);
        key[8*tI+2] = mapkey(2.f*pa1.x - xxr - xca.z);
        key[8*tI+3] = mapkey(2.f*pa1.y - xxr - xca.w);
        key[8*tI+4] = mapkey(2.f*pb0.x - xxr - xcb.x);
        key[8*tI+5] = mapkey(2.f*pb0.y - xxr - xcb.y);
        key[8*tI+6] = mapkey(2.f*pb1.x - xxr - xcb.z);
        key[8*tI+7] = mapkey(2.f*pb1.y - xxr - xcb.w);
    }

    // ---- selection: REDUX argmax with per-lane sorted top-4 cache ----
    unsigned ck0=0,ck1=0,ck2=0,ck3=0;
    unsigned ci0=0,ci1=0,ci2=0,ci3=0;
    #pragma unroll
    for (int j = 0; j < 32; j++) {
        unsigned k = key[j];
        unsigned gi = gi_of(j, lane);
        if (k > ck3) {
            if (k > ck0)      { ck3=ck2;ci3=ci2; ck2=ck1;ci2=ci1; ck1=ck0;ci1=ci0; ck0=k;ci0=gi; }
            else if (k > ck1) { ck3=ck2;ci3=ci2; ck2=ck1;ci2=ci1; ck1=k;ci1=gi; }
            else if (k > ck2) { ck3=ck2;ci3=ci2; ck2=k;ci2=gi; }
            else              { ck3=k;ci3=gi; }
        }
    }
    unsigned removed = 0u;
    int navail = 4;
    for (int sel = 0; sel < KNN; sel++) {
        unsigned maxk = __reduce_max_sync(0xffffffffu, ck0);
        unsigned cand = (ck0 == maxk) ? ci0 : 0xffffffffu;
        unsigned widx = __reduce_min_sync(0xffffffffu, cand);
        if (lane == 0) idxout[rowg * KNN + sel] = (int)widx;
        if (ck0 == maxk && ci0 == widx) {        // unique owner (gi unique)
            int jw = (int)(((widx >> 8) << 3) + (((widx >> 7) & 1u) << 2) + (widx & 3u));
            removed |= 1u << jw;
            ck0=ck1;ci0=ci1; ck1=ck2;ci1=ci2; ck2=ck3;ci2=ci3; ck3=0;ci3=0;
            if (--navail == 0) {                  // rare refill from registers
                ck0=ck1=ck2=ck3=0; ci0=ci1=ci2=ci3=0;
                #pragma unroll
                for (int j = 0; j < 32; j++) {
                    if ((removed >> j) & 1u) continue;
                    unsigned k = key[j];
                    unsigned gi = gi_of(j, lane);
                    if (k > ck3) {
                        if (k > ck0)      { ck3=ck2;ci3=ci2; ck2=ck1;ci2=ci1; ck1=ck0;ci1=ci0; ck0=k;ci0=gi; }
                        else if (k > ck1) { ck3=ck2;ci3=ci2; ck2=ck1;ci2=ci1; ck1=k;ci1=gi; }
                        else if (k > ck2) { ck3=ck2;ci3=ci2; ck2=k;ci2=gi; }
                        else              { ck3=k;ci3=gi; }
                    }
                }
                navail = 4;
            }
        }
    }
}

// ------------------------------------------------------------------ fused gather + edge conv + BN + leaky + max_k
// packed f32x2 FMA over output-channel pairs
template <int CIN, int CROW, int COUT, int P>
__global__ __launch_bounds__(128)
void conv_kernel(const float* __restrict__ X, const int* __restrict__ idx,
                 const float* __restrict__ w, const float* __restrict__ gam,
                 const float* __restrict__ bet, float* __restrict__ out) {
    constexpr int TPP = COUT / 4;
    constexpr int CP  = CROW + 4;
    extern __shared__ float sm[];
    float* wt = sm;                          // [CROW][COUT]  (w1^T, zero-padded c>=CIN)
    float* wd = wt + CROW * COUT;            // [CROW][COUT]  (w2-w1)^T
    float* nb = wd + CROW * COUT;            // [P][21][CP]
    int* sidx = (int*)(nb + P * 21 * CP);    // [P][KNN]

    int t = threadIdx.x;
    int b  = blockIdx.x / (NPT / P);
    int n0 = (blockIdx.x % (NPT / P)) * P;

    for (int i = t; i < CROW * COUT; i += 128) {
        int c = i / COUT, o = i % COUT;
        float w1 = (c < CIN) ? w[o * (2*CIN) + c] : 0.f;
        float w2 = (c < CIN) ? w[o * (2*CIN) + CIN + c] : 0.f;
        wt[c * COUT + o] = w1;
        wd[c * COUT + o] = w2 - w1;
    }
    for (int i = t; i < P * KNN; i += 128)
        sidx[i] = idx[((long)(b*NPT) + n0) * KNN + i];
    __syncthreads();

    constexpr int V4 = CROW / 4;
    for (int i = t; i < P * 21 * V4; i += 128) {
        int c4 = i % V4;
        int vec = i / V4;
        int p = vec / 21, k = vec % 21;
        int m = (k < KNN) ? sidx[p*KNN + k] : (n0 + p);
        float4 v = *(const float4*)&X[((long)(b*NPT) + m) * CROW + 4*c4];
        *(float4*)&nb[(p*21 + k) * CP + 4*c4] = v;
    }
    __syncthreads();

    int p  = t / TPP;
    int o4 = (t % TPP) * 4;
    unsigned long long s2[KNN][2];
    unsigned long long u2[2] = {0ull, 0ull};
    #pragma unroll
    for (int k = 0; k < KNN; k++) { s2[k][0] = 0ull; s2[k][1] = 0ull; }

    const float* nbp = nb + p * 21 * CP;
    #pragma unroll 1
    for (int c4i = 0; c4i < CROW/4; c4i++) {
        int c = 4 * c4i;
        ulonglong2 w1p[4], wdp[4];
        #pragma unroll
        for (int q = 0; q < 4; q++) {
            w1p[q] = *(const ulonglong2*)&wt[(c+q) * COUT + o4];
            wdp[q] = *(const ulonglong2*)&wd[(c+q) * COUT + o4];
        }
        float4 ct4 = *(const float4*)&nbp[20 * CP + c];
        unsigned long long ctd[4] = {dup2(ct4.x), dup2(ct4.y), dup2(ct4.z), dup2(ct4.w)};
        #pragma unroll
        for (int q = 0; q < 4; q++) {
            ffma2(u2[0], wdp[q].x, ctd[q]);
            ffma2(u2[1], wdp[q].y, ctd[q]);
        }
        #pragma unroll
        for (int k = 0; k < KNN; k++) {
            float4 nv = *(const float4*)&nbp[k * CP + c];
            unsigned long long n0d = dup2(nv.x), n1d = dup2(nv.y), n2d = dup2(nv.z), n3d = dup2(nv.w);
            ffma2(s2[k][0], w1p[0].x, n0d); ffma2(s2[k][1], w1p[0].y, n0d);
            ffma2(s2[k][0], w1p[1].x, n1d); ffma2(s2[k][1], w1p[1].y, n1d);
            ffma2(s2[k][0], w1p[2].x, n2d); ffma2(s2[k][1], w1p[2].y, n2d);
            ffma2(s2[k][0], w1p[3].x, n3d); ffma2(s2[k][1], w1p[3].y, n3d);
        }
    }
    float2 sxy = unpk2(s2[0][0]);
    float2 szw = unpk2(s2[0][1]);
    float4 mx = make_float4(sxy.x, sxy.y, szw.x, szw.y);
    float4 mn = mx;
    #pragma unroll
    for (int k = 1; k < KNN; k++) {
        float2 a = unpk2(s2[k][0]);
        float2 bq = unpk2(s2[k][1]);
        mx.x = fmaxf(mx.x, a.x);  mx.y = fmaxf(mx.y, a.y);
        mx.z = fmaxf(mx.z, bq.x); mx.w = fmaxf(mx.w, bq.y);
        mn.x = fminf(mn.x, a.x);  mn.y = fminf(mn.y, a.y);
        mn.z = fminf(mn.z, bq.x); mn.w = fminf(mn.w, bq.y);
    }
    float2 uxy = unpk2(u2[0]);
    float2 uzw = unpk2(u2[1]);
    float inv = rsqrtf(1.0f + 1e-5f);
    float4 gmv = *(const float4*)&gam[o4];
    float4 btv = *(const float4*)&bet[o4];
    float4 res;
    { float a = gmv.x*inv; float base = ((a>=0.f)?mx.x:mn.x) + uxy.x; float v = a*base + btv.x; res.x = v>=0.f?v:0.2f*v; }
    { float a = gmv.y*inv; float base = ((a>=0.f)?mx.y:mn.y) + uxy.y; float v = a*base + btv.y; res.y = v>=0.f?v:0.2f*v; }
    { float a = gmv.z*inv; float base = ((a>=0.f)?mx.z:mn.z) + uzw.x; float v = a*base + btv.z; res.z = v>=0.f?v:0.2f*v; }
    { float a = gmv.w*inv; float base = ((a>=0.f)?mx.w:mn.w) + uzw.y; float v = a*base + btv.w; res.w = v>=0.f?v:0.2f*v; }
    int n = n0 + p;
    *(float4*)&out[((long)(b*NPT) + n) * COUT + o4] = res;
}

// ------------------------------------------------------------------ ew conv on concat(H3,S3) -> emb (packed FMA)
__global__ __launch_bounds__(128)
void emb_kernel(const float* __restrict__ H3, const float* __restrict__ S3,
                const float* __restrict__ ew, const float* __restrict__ eg,
                const float* __restrict__ eb, float* __restrict__ emb) {
    extern __shared__ float sm[];
    float* wts  = sm;                 // [256][128]
    float* rows = wts + 256 * 128;    // [4][256]
    int t = threadIdx.x;
    for (int i = t; i < 256 * 128; i += 128) {
        int c = i / 128, o = i % 128;
        wts[c * 128 + o] = ew[o * 256 + c];
    }
    const int NITER = 8;
    int base = blockIdx.x * (4 * NITER);
    int pl = t / 32;
    int o4 = (t % 32) * 4;
    float inv = rsqrtf(1.0f + 1e-5f);
    for (int it = 0; it < NITER; it++) {
        __syncthreads();
        int p0 = base + it * 4;
        for (int i = t; i < 4 * 256; i += 128) {
            int pp = i / 256, c = i % 256;
            long pt = p0 + pp;
            rows[pp * 256 + c] = (c < 128) ? H3[pt * 128 + c] : S3[pt * 128 + c - 128];
        }
        __syncthreads();
        unsigned long long acc2[2] = {0ull, 0ull};
        for (int c = 0; c < 256; c++) {
            ulonglong2 wp = *(const ulonglong2*)&wts[c * 128 + o4];
            unsigned long long xd = dup2(rows[pl * 256 + c]);
            ffma2(acc2[0], wp.x, xd);
            ffma2(acc2[1], wp.y, xd);
        }
        float2 axy = unpk2(acc2[0]);
        float2 azw = unpk2(acc2[1]);
        float4 gmv = *(const float4*)&eg[o4];
        float4 btv = *(const float4*)&eb[o4];
        float4 r;
        { float v = gmv.x*inv*axy.x + btv.x; r.x = v>=0.f?v:0.2f*v; }
        { float v = gmv.y*inv*axy.y + btv.y; r.y = v>=0.f?v:0.2f*v; }
        { float v = gmv.z*inv*azw.x + btv.z; r.z = v>=0.f?v:0.2f*v; }
        { float v = gmv.w*inv*azw.y + btv.w; r.w = v>=0.f?v:0.2f*v; }
        long pt = p0 + pl;
        *(float4*)&emb[pt * 128 + o4] = r;
    }
}

// ------------------------------------------------------------------ attention pieces
__global__ void colsum_part(const float* __restrict__ emb, float* __restrict__ part) {
    int b = blockIdx.x, seg = blockIdx.y, f = threadIdx.x;
    const float* p = emb + ((long)(b*NPT) + seg*128) * 128 + f;
    float a = 0.f;
    #pragma unroll 4
    for (int n = 0; n < 128; n++) a += p[n * 128];
    part[(b*8 + seg) * 128 + f] = a;
}

__global__ void gc2_kernel(const float* __restrict__ part, const float* __restrict__ att_w,
                           float* __restrict__ gc) {
    __shared__ float es[128];
    int b = blockIdx.x, t = threadIdx.x;
    float a = 0.f;
    #pragma unroll
    for (int s = 0; s < 8; s++) a += part[(b*8 + s) * 128 + t];
    es[t] = a;
    __syncthreads();
    float gv = 0.f;
    for (int f = 0; f < 128; f++) gv += es[f] * att_w[f * 128 + t];
    gc[b * 128 + t] = tanhf(gv * (1.0f / NPT));
}

__global__ void sc_kernel(const float* __restrict__ emb, const float* __restrict__ gc,
                          float* __restrict__ att) {
    int warp = threadIdx.x >> 5, lane = threadIdx.x & 31;
    int pid = blockIdx.x * 4 + warp;
    int b = pid >> 10;
    float a = 0.f;
    #pragma unroll
    for (int j = 0; j < 4; j++) {
        int f = lane + 32 * j;
        a += emb[(long)pid * 128 + f] * gc[b * 128 + f];
    }
    #pragma unroll
    for (int off = 16; off; off >>= 1) a += __shfl_down_sync(0xffffffffu, a, off);
    if (lane == 0) att[pid] = 1.0f / (1.0f + expf(-a));
}

__global__ void pool_part(const float* __restrict__ emb, const float* __restrict__ att,
                          float* __restrict__ part) {
    int b = blockIdx.x, seg = blockIdx.y, f = threadIdx.x;
    const float* p = emb + ((long)(b*NPT) + seg*128) * 128 + f;
    const float* aw = att + b*NPT + seg*128;
    float a = 0.f;
    #pragma unroll 4
    for (int n = 0; n < 128; n++) a += p[n * 128] * aw[n];
    part[(b*8 + seg) * 128 + f] = a;
}

__global__ void pool_fin(const float* __restrict__ part, float* __restrict__ e) {
    int b = blockIdx.x, t = threadIdx.x;
    float a = 0.f;
    #pragma unroll
    for (int s = 0; s < 8; s++) a += part[(b*8 + s) * 128 + t];
    e[b * 128 + t] = a;
}

// ------------------------------------------------------------------ final scoring
__global__ void final_kernel(const float* __restrict__ e, const float* __restrict__ tn_w,
                             const float* __restrict__ tn_wb, const float* __restrict__ tn_bias,
                             const float* __restrict__ fc1_w, const float* __restrict__ fc1_b,
                             const float* __restrict__ sc_w, const float* __restrict__ sc_b,
                             float* __restrict__ out) {
    __shared__ float e1s[128], e2s[128], red[128], ts[16], hs[16];
    int b = blockIdx.x, tid = threadIdx.x;
    e1s[tid] = e[b * 128 + tid];
    e2s[tid] = e[(b + 8) * 128 + tid];
    __syncthreads();
    for (int tt = 0; tt < 16; tt++) {
        float inner = 0.f;
        const float* wrow = tn_w + (long)tid * 128 * 16 + tt;
        for (int gI = 0; gI < 128; gI++) inner += wrow[gI * 16] * e2s[gI];
        red[tid] = e1s[tid] * inner;
        __syncthreads();
        for (int s2 = 64; s2; s2 >>= 1) {
            if (tid < s2) red[tid] += red[tid + s2];
            __syncthreads();
        }
        if (tid == 0) ts[tt] = red[0];
        __syncthreads();
    }
    if (tid < 16) {
        float blk = 0.f;
        for (int c = 0; c < 128; c++) blk += tn_wb[tid * 256 + c] * e1s[c];
        for (int c = 0; c < 128; c++) blk += tn_wb[tid * 256 + 128 + c] * e2s[c];
        float v = ts[tid] + blk + tn_bias[tid];
        ts[tid] = v > 0.f ? v : 0.f;
    }
    __syncthreads();
    if (tid < 16) {
        float h = fc1_b[tid];
        for (int u2 = 0; u2 < 16; u2++) h += fc1_w[tid * 16 + u2] * ts[u2];
        hs[tid] = h > 0.f ? h : 0.f;
    }
    __syncthreads();
    if (tid == 0) {
        float z = sc_b[0];
        for (int u2 = 0; u2 < 16; u2++) z += sc_w[u2] * hs[u2];
        out[b] = 1.0f / (1.0f + expf(-z));
    }
}

// ------------------------------------------------------------------ host
template <typename T>
static float* symaddr(T& sym_) {
    void* p = nullptr;
    cudaGetSymbolAddress(&p, sym_);
    return (float*)p;
}

extern "C" void kernel_launch(void* const* d_in, const int* in_sizes, int n_in,
                              void* d_out, int out_size) {
    (void)in_sizes; (void)n_in; (void)out_size;
    const float* f1    = (const float*)d_in[0];
    const float* f2    = (const float*)d_in[1];
    const float* sw1   = (const float*)d_in[2];
    const float* sg1   = (const float*)d_in[3];
    const float* sb1   = (const float*)d_in[4];
    const float* fw1   = (const float*)d_in[5];
    const float* fg1   = (const float*)d_in[6];
    const float* fb1   = (const float*)d_in[7];
    const float* sw2   = (const float*)d_in[8];
    const float* sg2   = (const float*)d_in[9];
    const float* sb2   = (const float*)d_in[10];
    const float* fw2   = (const float*)d_in[11];
    const float* fg2   = (const float*)d_in[12];
    const float* fb2   = (const float*)d_in[13];
    const float* sw3   = (const float*)d_in[14];
    const float* sg3   = (const float*)d_in[15];
    const float* sb3   = (const float*)d_in[16];
    const float* fw3   = (const float*)d_in[17];
    const float* fg3   = (const float*)d_in[18];
    const float* fb3   = (const float*)d_in[19];
    const float* ew    = (const float*)d_in[20];
    const float* eg    = (const float*)d_in[21];
    const float* ebv   = (const float*)d_in[22];
    const float* att_w = (const float*)d_in[23];
    const float* tn_w  = (const float*)d_in[24];
    const float* tn_wb = (const float*)d_in[25];
    const float* tn_b  = (const float*)d_in[26];
    const float* fc1_w = (const float*)d_in[27];
    const float* fc1_b = (const float*)d_in[28];
    const float* sc_w  = (const float*)d_in[29];
    const float* sc_b  = (const float*)d_in[30];
    float* out = (float*)d_out;

    int*   idxp  = (int*)symaddr(g_idx);
    float* xxp   = symaddr(g_xx);
    float* x0p   = symaddr(g_x0);
    float* s0p   = symaddr(g_s0);
    float* h1p   = symaddr(g_h1);
    float* h2p   = symaddr(g_h2);
    float* h3p   = symaddr(g_h3);
    float* embp  = symaddr(g_emb);
    float* partp = symaddr(g_part);
    float* gcp   = symaddr(g_gc);
    float* ep    = symaddr(g_e);

    const int SM_C1 = (2*4*64    + 8*21*8  ) * 4 + 8*KNN*4;   // conv<3,4,64,8>
    const int SM_C2 = (2*64*64   + 8*21*68 ) * 4 + 8*KNN*4;   // conv<64,64,64,8>
    const int SM_C3 = (2*64*128  + 4*21*68 ) * 4 + 4*KNN*4;   // conv<64,64,128,4>
    const int SM_C4 = (2*128*64  + 8*21*132) * 4 + 8*KNN*4;   // conv<128,128,64,8>
    const int SM_EW = (256*128 + 4*256) * 4;
    const int SM_K4   = (4*256   + 16*4   + 256) * 4;
    const int SM_K64  = (64*256  + 16*64  + 256) * 4;
    const int SM_K128 = (128*256 + 16*128 + 256) * 4;

    cudaFuncSetAttribute(conv_kernel<64,64,64,8>,   cudaFuncAttributeMaxDynamicSharedMemorySize, SM_C2);
    cudaFuncSetAttribute(conv_kernel<64,64,128,4>,  cudaFuncAttributeMaxDynamicSharedMemorySize, SM_C3);
    cudaFuncSetAttribute(conv_kernel<128,128,64,8>, cudaFuncAttributeMaxDynamicSharedMemorySize, SM_C4);
    cudaFuncSetAttribute(emb_kernel,                cudaFuncAttributeMaxDynamicSharedMemorySize, SM_EW);
    cudaFuncSetAttribute(knn_kernel<64>,            cudaFuncAttributeMaxDynamicSharedMemorySize, SM_K64);
    cudaFuncSetAttribute(knn_kernel<128>,           cudaFuncAttributeMaxDynamicSharedMemorySize, SM_K128);

    transpose_kernel<<<(NB*131*NPT + 255) / 256, 256>>>(f1, f2, x0p, s0p);

    // ---- xyz chain: 3 -> 64 -> 64 -> 128 ----
    xx_kernel<4><<<NROW/256, 256>>>(x0p, xxp);
    knn_kernel<4><<<NROW/16, 512, SM_K4>>>(x0p, xxp, idxp);
    conv_kernel<3,4,64,8><<<NB*NPT/8, 128, SM_C1>>>(x0p, idxp, sw1, sg1, sb1, h1p);

    xx_kernel<64><<<NROW/256, 256>>>(h1p, xxp);
    knn_kernel<64><<<NROW/16, 512, SM_K64>>>(h1p, xxp, idxp);
    conv_kernel<64,64,64,8><<<NB*NPT/8, 128, SM_C2>>>(h1p, idxp, sw2, sg2, sb2, h2p);

    xx_kernel<64><<<NROW/256, 256>>>(h2p, xxp);
    knn_kernel<64><<<NROW/16, 512, SM_K64>>>(h2p, xxp, idxp);
    conv_kernel<64,64,128,4><<<NB*NPT/4, 128, SM_C3>>>(h2p, idxp, sw3, sg3, sb3, h3p);

    // ---- sem chain: 128 -> 64 -> 64 -> 128 ----
    xx_kernel<128><<<NROW/256, 256>>>(s0p, xxp);
    knn_kernel<128><<<NROW/16, 512, SM_K128>>>(s0p, xxp, idxp);
    conv_kernel<128,128,64,8><<<NB*NPT/8, 128, SM_C4>>>(s0p, idxp, fw1, fg1, fb1, h1p);

    xx_kernel<64><<<NROW/256, 256>>>(h1p, xxp);
    knn_kernel<64><<<NROW/16, 512, SM_K64>>>(h1p, xxp, idxp);
    conv_kernel<64,64,64,8><<<NB*NPT/8, 128, SM_C2>>>(h1p, idxp, fw2, fg2, fb2, h2p);

    xx_kernel<64><<<NROW/256, 256>>>(h2p, xxp);
    knn_kernel<64><<<NROW/16, 512, SM_K64>>>(h2p, xxp, idxp);
    conv_kernel<64,64,128,4><<<NB*NPT/4, 128, SM_C3>>>(h2p, idxp, fw3, fg3, fb3, s0p);  // s0p reused as S3

    // ---- fuse + attention (all 16 batches) ----
    emb_kernel<<<NROW/32, 128, SM_EW>>>(h3p, s0p, ew, eg, ebv, embp);

    float* att_out = out + 8;                       // att1 (b 0..7) then att2 (b 8..15), contiguous
    colsum_part<<<dim3(NB, 8), 128>>>(embp, partp);
    gc2_kernel<<<NB, 128>>>(partp, att_w, gcp);
    sc_kernel<<<NROW/4, 128>>>(embp, gcp, att_out);
    pool_part<<<dim3(NB, 8), 128>>>(embp, att_out, partp);
    pool_fin<<<NB, 128>>>(partp, ep);

    final_kernel<<<BB, 128>>>(ep, tn_w, tn_wb, tn_b, fc1_w, fc1_b, sc_w, sc_b, out);
}

// round 8
// speedup vs baseline: 1.4340x; 1.4340x over previous
#include <cuda_runtime.h>
#include <math.h>
#include <stdint.h>

#define BB   8
#define NB   16          // both graphs merged into one batch
#define NPT  1024
#define KNN  20
#define NROW (NB*NPT)    // 16384

// ------------------------------------------------------------------ packed fp32x2 helpers
__device__ __forceinline__ void ffma2(unsigned long long& d, unsigned long long a, unsigned long long b) {
    asm("fma.rn.f32x2 %0, %1, %2, %0;" : "+l"(d) : "l"(a), "l"(b));
}
__device__ __forceinline__ unsigned long long dup2(float x) {
    unsigned long long r;
    asm("mov.b64 %0, {%1, %1};" : "=l"(r) : "f"(x));
    return r;
}
__device__ __forceinline__ float2 unpk2(unsigned long long v) {
    float2 r;
    asm("mov.b64 {%0, %1}, %2;" : "=f"(r.x), "=f"(r.y) : "l"(v));
    return r;
}
__device__ __forceinline__ unsigned mapkey(float v) {
    unsigned u = __float_as_uint(v);
    return (u & 0x80000000u) ? ~u : (u | 0x80000000u);   // order-preserving; real keys > 0
}

// ------------------------------------------------------------------ scratch
__device__ unsigned g_neg[NROW*NPT];   // 64 MB mapped-key distance matrix (reused)
__device__ int   g_idx[NROW*KNN];
__device__ float g_xx [NROW];
__device__ float g_x0 [NROW*4];
__device__ float g_s0 [NROW*128];
__device__ float g_h1 [NROW*64];
__device__ float g_h2 [NROW*64];
__device__ float g_h3 [NROW*128];
__device__ float g_emb[NROW*128];
__device__ float g_part[NB*8*128];
__device__ float g_gc  [NB*128];
__device__ float g_e   [NB*128];

// ------------------------------------------------------------------ transpose both inputs (B,C,N) -> point-major
__global__ void transpose_kernel(const float* __restrict__ f1, const float* __restrict__ f2,
                                 float* __restrict__ x0, float* __restrict__ s0) {
    int j = blockIdx.x * blockDim.x + threadIdx.x;
    int total = NB * 131 * NPT;
    if (j >= total) return;
    int n = j % NPT;
    int c = (j / NPT) % 131;
    int b = j / (131 * NPT);
    const float* in = (b < BB) ? f1 : f2;
    float v = in[((long)(b & 7) * 131 + c) * NPT + n];
    if (c < 3) {
        x0[(b*NPT + n)*4 + c] = v;
        if (c == 0) x0[(b*NPT + n)*4 + 3] = 0.0f;
    } else {
        s0[((long)(b*NPT) + n)*128 + (c - 3)] = v;
    }
}

// ------------------------------------------------------------------ per-point squared norm
template <int CROW>
__global__ void xx_kernel(const float* __restrict__ X, float* __restrict__ xx) {
    int j = blockIdx.x * 256 + threadIdx.x;
    if (j >= NROW) return;
    const float* r = X + (long)j * CROW;
    float a = 0.f;
    #pragma unroll
    for (int c = 0; c < CROW; c++) a += r[c] * r[c];
    xx[j] = a;
}

// ------------------------------------------------------------------ neg distance -> mapped u32 keys
// 128x128 tile, 256 threads, 8x8 register micro-tile, packed f32x2 FMA
template <int CROW>
__global__ __launch_bounds__(256, 1) void dist_kernel(const float* __restrict__ X,
                                                      const float* __restrict__ xx,
                                                      unsigned* __restrict__ neg) {
    constexpr int TC = (CROW < 16) ? CROW : 16;
    constexpr int LDW = 132;
    __shared__ float As[TC][LDW];
    __shared__ float Bs[TC][LDW];
    int b = blockIdx.z;
    int row0 = blockIdx.y * 128;
    int col0 = blockIdx.x * 128;
    int t = threadIdx.x;
    int tx = t & 15, ty = t >> 4;
    unsigned long long acc2[8][4];
    #pragma unroll
    for (int i = 0; i < 8; i++)
        #pragma unroll
        for (int j = 0; j < 4; j++) acc2[i][j] = 0ull;

    for (int c0 = 0; c0 < CROW; c0 += TC) {
        constexpr int NLD = (128 * TC) / 256;
        #pragma unroll
        for (int l = 0; l < NLD; l++) {
            int i = t + l * 256;
            int r = i / TC, c = i % TC;
            As[c][r] = X[((long)(b*NPT) + row0 + r) * CROW + c0 + c];
            Bs[c][r] = X[((long)(b*NPT) + col0 + r) * CROW + c0 + c];
        }
        __syncthreads();
        #pragma unroll
        for (int c = 0; c < TC; c++) {
            float4 a0 = *(const float4*)&As[c][ty*8];
            float4 a1 = *(const float4*)&As[c][ty*8+4];
            ulonglong2 b01 = *(const ulonglong2*)&Bs[c][tx*8];
            ulonglong2 b23 = *(const ulonglong2*)&Bs[c][tx*8+4];
            unsigned long long bp[4] = {b01.x, b01.y, b23.x, b23.y};
            unsigned long long ap[8];
            ap[0]=dup2(a0.x); ap[1]=dup2(a0.y); ap[2]=dup2(a0.z); ap[3]=dup2(a0.w);
            ap[4]=dup2(a1.x); ap[5]=dup2(a1.y); ap[6]=dup2(a1.z); ap[7]=dup2(a1.w);
            #pragma unroll
            for (int i = 0; i < 8; i++)
                #pragma unroll
                for (int j = 0; j < 4; j++) ffma2(acc2[i][j], ap[i], bp[j]);
        }
        __syncthreads();
    }
    float xr[8], xc[8];
    #pragma unroll
    for (int i = 0; i < 8; i++) {
        xr[i] = xx[b*NPT + row0 + ty*8 + i];
        xc[i] = xx[b*NPT + col0 + tx*8 + i];
    }
    #pragma unroll
    for (int i = 0; i < 8; i++) {
        long rbase = ((long)(b*NPT) + row0 + ty*8 + i) * NPT + col0 + tx*8;
        float2 p0 = unpk2(acc2[i][0]);
        float2 p1 = unpk2(acc2[i][1]);
        float2 p2 = unpk2(acc2[i][2]);
        float2 p3 = unpk2(acc2[i][3]);
        uint4 o0, o1;
        o0.x = mapkey(2.f*p0.x - xr[i] - xc[0]);
        o0.y = mapkey(2.f*p0.y - xr[i] - xc[1]);
        o0.z = mapkey(2.f*p1.x - xr[i] - xc[2]);
        o0.w = mapkey(2.f*p1.y - xr[i] - xc[3]);
        o1.x = mapkey(2.f*p2.x - xr[i] - xc[4]);
        o1.y = mapkey(2.f*p2.y - xr[i] - xc[5]);
        o1.z = mapkey(2.f*p3.x - xr[i] - xc[6]);
        o1.w = mapkey(2.f*p3.y - xr[i] - xc[7]);
        *(uint4*)&neg[rbase]     = o0;
        *(uint4*)&neg[rbase + 4] = o1;
    }
}

// ------------------------------------------------------------------ top-20: warp per row, REDUX argmax + per-lane top-4 cache
// neg already holds order-preserving u32 keys (> 0).
__global__ __launch_bounds__(256) void topk_kernel(const unsigned* __restrict__ neg, int* __restrict__ idxout) {
    int warp = threadIdx.x >> 5, lane = threadIdx.x & 31;
    int row = blockIdx.x * 8 + warp;
    const unsigned* rp = neg + (long)row * NPT;

    unsigned ck0=0,ck1=0,ck2=0,ck3=0;
    unsigned ci0=0,ci1=0,ci2=0,ci3=0;
    #pragma unroll
    for (int j = 0; j < 32; j++) {
        unsigned k = rp[lane + 32*j];
        unsigned gi = (unsigned)(lane + 32*j);
        if (k > ck3) {
            if (k > ck0)      { ck3=ck2;ci3=ci2; ck2=ck1;ci2=ci1; ck1=ck0;ci1=ci0; ck0=k;ci0=gi; }
            else if (k > ck1) { ck3=ck2;ci3=ci2; ck2=ck1;ci2=ci1; ck1=k;ci1=gi; }
            else if (k > ck2) { ck3=ck2;ci3=ci2; ck2=k;ci2=gi; }
            else              { ck3=k;ci3=gi; }
        }
    }
    unsigned removed = 0u;
    int navail = 4;
    for (int sel = 0; sel < KNN; sel++) {
        unsigned maxk = __reduce_max_sync(0xffffffffu, ck0);
        unsigned cand = (ck0 == maxk) ? ci0 : 0xffffffffu;
        unsigned widx = __reduce_min_sync(0xffffffffu, cand);
        if (lane == 0) idxout[row*KNN + sel] = (int)widx;
        if (ck0 == maxk && ci0 == widx) {        // unique owner
            removed |= 1u << (widx >> 5);
            ck0=ck1;ci0=ci1; ck1=ck2;ci1=ci2; ck2=ck3;ci2=ci3; ck3=0;ci3=0;
            if (--navail == 0) {                  // rare refill (lane needed 5+ wins)
                ck0=ck1=ck2=ck3=0; ci0=ci1=ci2=ci3=0;
                for (int j = 0; j < 32; j++) {
                    if ((removed >> j) & 1u) continue;
                    unsigned k = rp[lane + 32*j];
                    unsigned gi = (unsigned)(lane + 32*j);
                    if (k > ck3) {
                        if (k > ck0)      { ck3=ck2;ci3=ci2; ck2=ck1;ci2=ci1; ck1=ck0;ci1=ci0; ck0=k;ci0=gi; }
                        else if (k > ck1) { ck3=ck2;ci3=ci2; ck2=ck1;ci2=ci1; ck1=k;ci1=gi; }
                        else if (k > ck2) { ck3=ck2;ci3=ci2; ck2=k;ci2=gi; }
                        else              { ck3=k;ci3=gi; }
                    }
                }
                navail = 4;
            }
        }
    }
}

// ------------------------------------------------------------------ fused gather + edge conv + BN + leaky + max_k
// packed f32x2 FMA; CPT = output channels per thread (4 or 2); no accumulator spill (minBlocks=1)
template <int CIN, int CROW, int COUT, int P, int THREADS>
__global__ __launch_bounds__(THREADS, 1)
void conv_kernel(const float* __restrict__ X, const int* __restrict__ idx,
                 const float* __restrict__ w, const float* __restrict__ gam,
                 const float* __restrict__ bet, float* __restrict__ out) {
    constexpr int TPP = THREADS / P;
    constexpr int CPT = COUT / TPP;
    constexpr int NA  = CPT / 2;
    constexpr int CP  = CROW + 4;
    extern __shared__ float sm[];
    float* wt = sm;                          // [CROW][COUT]  (w1^T, zero-padded c>=CIN)
    float* wd = wt + CROW * COUT;            // [CROW][COUT]  (w2-w1)^T
    float* nb = wd + CROW * COUT;            // [P][21][CP]
    int* sidx = (int*)(nb + P * 21 * CP);    // [P][KNN]

    int t = threadIdx.x;
    int b  = blockIdx.x / (NPT / P);
    int n0 = (blockIdx.x % (NPT / P)) * P;

    for (int i = t; i < CROW * COUT; i += THREADS) {
        int c = i / COUT, o = i % COUT;
        float w1 = (c < CIN) ? w[o * (2*CIN) + c] : 0.f;
        float w2 = (c < CIN) ? w[o * (2*CIN) + CIN + c] : 0.f;
        wt[c * COUT + o] = w1;
        wd[c * COUT + o] = w2 - w1;
    }
    for (int i = t; i < P * KNN; i += THREADS)
        sidx[i] = idx[((long)(b*NPT) + n0) * KNN + i];
    __syncthreads();

    constexpr int V4 = CROW / 4;
    for (int i = t; i < P * 21 * V4; i += THREADS) {
        int c4 = i % V4;
        int vec = i / V4;
        int p = vec / 21, k = vec % 21;
        int m = (k < KNN) ? sidx[p*KNN + k] : (n0 + p);
        float4 v = *(const float4*)&X[((long)(b*NPT) + m) * CROW + 4*c4];
        *(float4*)&nb[(p*21 + k) * CP + 4*c4] = v;
    }
    __syncthreads();

    int p  = t / TPP;
    int o0 = (t % TPP) * CPT;
    unsigned long long s2[KNN][NA];
    unsigned long long u2[NA];
    #pragma unroll
    for (int k = 0; k < KNN; k++)
        #pragma unroll
        for (int a = 0; a < NA; a++) s2[k][a] = 0ull;
    #pragma unroll
    for (int a = 0; a < NA; a++) u2[a] = 0ull;

    const float* nbp = nb + p * 21 * CP;
    #pragma unroll 1
    for (int c4i = 0; c4i < CROW/4; c4i++) {
        int c = 4 * c4i;
        unsigned long long w1p[4][NA], wdp[4][NA];
        #pragma unroll
        for (int q = 0; q < 4; q++)
            #pragma unroll
            for (int a = 0; a < NA; a++) {
                w1p[q][a] = *(const unsigned long long*)&wt[(c+q) * COUT + o0 + 2*a];
                wdp[q][a] = *(const unsigned long long*)&wd[(c+q) * COUT + o0 + 2*a];
            }
        float4 ct4 = *(const float4*)&nbp[20 * CP + c];
        unsigned long long ctd[4] = {dup2(ct4.x), dup2(ct4.y), dup2(ct4.z), dup2(ct4.w)};
        #pragma unroll
        for (int q = 0; q < 4; q++)
            #pragma unroll
            for (int a = 0; a < NA; a++) ffma2(u2[a], wdp[q][a], ctd[q]);
        #pragma unroll
        for (int k = 0; k < KNN; k++) {
            float4 nv = *(const float4*)&nbp[k * CP + c];
            unsigned long long nd[4] = {dup2(nv.x), dup2(nv.y), dup2(nv.z), dup2(nv.w)};
            #pragma unroll
            for (int q = 0; q < 4; q++)
                #pragma unroll
                for (int a = 0; a < NA; a++) ffma2(s2[k][a], w1p[q][a], nd[q]);
        }
    }
    float inv = rsqrtf(1.0f + 1e-5f);
    float res[CPT];
    #pragma unroll
    for (int a = 0; a < NA; a++) {
        float2 m0 = unpk2(s2[0][a]);
        float2 mx = m0, mn = m0;
        #pragma unroll
        for (int k = 1; k < KNN; k++) {
            float2 v = unpk2(s2[k][a]);
            mx.x = fmaxf(mx.x, v.x); mx.y = fmaxf(mx.y, v.y);
            mn.x = fminf(mn.x, v.x); mn.y = fminf(mn.y, v.y);
        }
        float2 uv = unpk2(u2[a]);
        float g0 = gam[o0 + 2*a], g1 = gam[o0 + 2*a + 1];
        float b0 = bet[o0 + 2*a], b1 = bet[o0 + 2*a + 1];
        { float aa = g0*inv; float base = ((aa>=0.f)?mx.x:mn.x) + uv.x; float v = aa*base + b0; res[2*a]   = v>=0.f?v:0.2f*v; }
        { float aa = g1*inv; float base = ((aa>=0.f)?mx.y:mn.y) + uv.y; float v = aa*base + b1; res[2*a+1] = v>=0.f?v:0.2f*v; }
    }
    int n = n0 + p;
    float* op = &out[((long)(b*NPT) + n) * COUT + o0];
    if constexpr (NA == 2) {
        *(float4*)op = make_float4(res[0], res[1], res[2], res[3]);
    } else {
        *(float2*)op = make_float2(res[0], res[1]);
    }
}

// ------------------------------------------------------------------ ew conv on concat(H3,S3) -> emb (packed FMA)
__global__ __launch_bounds__(128)
void emb_kernel(const float* __restrict__ H3, const float* __restrict__ S3,
                const float* __restrict__ ew, const float* __restrict__ eg,
                const float* __restrict__ eb, float* __restrict__ emb) {
    extern __shared__ float sm[];
    float* wts  = sm;                 // [256][128]
    float* rows = wts + 256 * 128;    // [4][256]
    int t = threadIdx.x;
    for (int i = t; i < 256 * 128; i += 128) {
        int c = i / 128, o = i % 128;
        wts[c * 128 + o] = ew[o * 256 + c];
    }
    const int NITER = 8;
    int base = blockIdx.x * (4 * NITER);
    int pl = t / 32;
    int o4 = (t % 32) * 4;
    float inv = rsqrtf(1.0f + 1e-5f);
    for (int it = 0; it < NITER; it++) {
        __syncthreads();
        int p0 = base + it * 4;
        for (int i = t; i < 4 * 256; i += 128) {
            int pp = i / 256, c = i % 256;
            long pt = p0 + pp;
            rows[pp * 256 + c] = (c < 128) ? H3[pt * 128 + c] : S3[pt * 128 + c - 128];
        }
        __syncthreads();
        unsigned long long acc2[2] = {0ull, 0ull};
        for (int c = 0; c < 256; c++) {
            ulonglong2 wp = *(const ulonglong2*)&wts[c * 128 + o4];
            unsigned long long xd = dup2(rows[pl * 256 + c]);
            ffma2(acc2[0], wp.x, xd);
            ffma2(acc2[1], wp.y, xd);
        }
        float2 axy = unpk2(acc2[0]);
        float2 azw = unpk2(acc2[1]);
        float4 gmv = *(const float4*)&eg[o4];
        float4 btv = *(const float4*)&eb[o4];
        float4 r;
        { float v = gmv.x*inv*axy.x + btv.x; r.x = v>=0.f?v:0.2f*v; }
        { float v = gmv.y*inv*axy.y + btv.y; r.y = v>=0.f?v:0.2f*v; }
        { float v = gmv.z*inv*azw.x + btv.z; r.z = v>=0.f?v:0.2f*v; }
        { float v = gmv.w*inv*azw.y + btv.w; r.w = v>=0.f?v:0.2f*v; }
        long pt = p0 + pl;
        *(float4*)&emb[pt * 128 + o4] = r;
    }
}

// ------------------------------------------------------------------ attention pieces
// fused colsum + gc (identical summation order to the two-kernel version)
__global__ void gcfused_kernel(const float* __restrict__ emb, const float* __restrict__ att_w,
                               float* __restrict__ gc) {
    __shared__ float part[8][128];
    __shared__ float es[128];
    int b = blockIdx.x, t = threadIdx.x;      // 1024 threads
    int seg = t >> 7, f = t & 127;
    const float* p = emb + ((long)(b*NPT) + seg*128) * 128 + f;
    float a = 0.f;
    #pragma unroll 4
    for (int n = 0; n < 128; n++) a += p[n * 128];
    part[seg][f] = a;
    __syncthreads();
    if (t < 128) {
        float s = 0.f;
        #pragma unroll
        for (int s8 = 0; s8 < 8; s8++) s += part[s8][t];
        es[t] = s;
    }
    __syncthreads();
    if (t < 128) {
        float gv = 0.f;
        for (int f2 = 0; f2 < 128; f2++) gv += es[f2] * att_w[f2 * 128 + t];
        gc[b * 128 + t] = tanhf(gv * (1.0f / NPT));
    }
}

__global__ void sc_kernel(const float* __restrict__ emb, const float* __restrict__ gc,
                          float* __restrict__ att) {
    int warp = threadIdx.x >> 5, lane = threadIdx.x & 31;
    int pid = blockIdx.x * 4 + warp;
    int b = pid >> 10;
    float a = 0.f;
    #pragma unroll
    for (int j = 0; j < 4; j++) {
        int f = lane + 32 * j;
        a += emb[(long)pid * 128 + f] * gc[b * 128 + f];
    }
    #pragma unroll
    for (int off = 16; off; off >>= 1) a += __shfl_down_sync(0xffffffffu, a, off);
    if (lane == 0) att[pid] = 1.0f / (1.0f + expf(-a));
}

__global__ void pool_part(const float* __restrict__ emb, const float* __restrict__ att,
                          float* __restrict__ part) {
    int b = blockIdx.x, seg = blockIdx.y, f = threadIdx.x;
    const float* p = emb + ((long)(b*NPT) + seg*128) * 128 + f;
    const float* aw = att + b*NPT + seg*128;
    float a = 0.f;
    #pragma unroll 4
    for (int n = 0; n < 128; n++) a += p[n * 128] * aw[n];
    part[(b*8 + seg) * 128 + f] = a;
}

__global__ void pool_fin(const float* __restrict__ part, float* __restrict__ e) {
    int b = blockIdx.x, t = threadIdx.x;
    float a = 0.f;
    #pragma unroll
    for (int s = 0; s < 8; s++) a += part[(b*8 + s) * 128 + t];
    e[b * 128 + t] = a;
}

// ------------------------------------------------------------------ final scoring
__global__ void final_kernel(const float* __restrict__ e, const float* __restrict__ tn_w,
                             const float* __restrict__ tn_wb, const float* __restrict__ tn_bias,
                             const float* __restrict__ fc1_w, const float* __restrict__ fc1_b,
                             const float* __restrict__ sc_w, const float* __restrict__ sc_b,
                             float* __restrict__ out) {
    __shared__ float e1s[128], e2s[128], red[128], ts[16], hs[16];
    int b = blockIdx.x, tid = threadIdx.x;
    e1s[tid] = e[b * 128 + tid];
    e2s[tid] = e[(b + 8) * 128 + tid];
    __syncthreads();
    for (int tt = 0; tt < 16; tt++) {
        float inner = 0.f;
        const float* wrow = tn_w + (long)tid * 128 * 16 + tt;
        for (int gI = 0; gI < 128; gI++) inner += wrow[gI * 16] * e2s[gI];
        red[tid] = e1s[tid] * inner;
        __syncthreads();
        for (int s2 = 64; s2; s2 >>= 1) {
            if (tid < s2) red[tid] += red[tid + s2];
            __syncthreads();
        }
        if (tid == 0) ts[tt] = red[0];
        __syncthreads();
    }
    if (tid < 16) {
        float blk = 0.f;
        for (int c = 0; c < 128; c++) blk += tn_wb[tid * 256 + c] * e1s[c];
        for (int c = 0; c < 128; c++) blk += tn_wb[tid * 256 + 128 + c] * e2s[c];
        float v = ts[tid] + blk + tn_bias[tid];
        ts[tid] = v > 0.f ? v : 0.f;
    }
    __syncthreads();
    if (tid < 16) {
        float h = fc1_b[tid];
        for (int u2 = 0; u2 < 16; u2++) h += fc1_w[tid * 16 + u2] * ts[u2];
        hs[tid] = h > 0.f ? h : 0.f;
    }
    __syncthreads();
    if (tid == 0) {
        float z = sc_b[0];
        for (int u2 = 0; u2 < 16; u2++) z += sc_w[u2] * hs[u2];
        out[b] = 1.0f / (1.0f + expf(-z));
    }
}

// ------------------------------------------------------------------ host
template <typename T>
static float* symaddr(T& sym_) {
    void* p = nullptr;
    cudaGetSymbolAddress(&p, sym_);
    return (float*)p;
}

extern "C" void kernel_launch(void* const* d_in, const int* in_sizes, int n_in,
                              void* d_out, int out_size) {
    (void)in_sizes; (void)n_in; (void)out_size;
    const float* f1    = (const float*)d_in[0];
    const float* f2    = (const float*)d_in[1];
    const float* sw1   = (const float*)d_in[2];
    const float* sg1   = (const float*)d_in[3];
    const float* sb1   = (const float*)d_in[4];
    const float* fw1   = (const float*)d_in[5];
    const float* fg1   = (const float*)d_in[6];
    const float* fb1   = (const float*)d_in[7];
    const float* sw2   = (const float*)d_in[8];
    const float* sg2   = (const float*)d_in[9];
    const float* sb2   = (const float*)d_in[10];
    const float* fw2   = (const float*)d_in[11];
    const float* fg2   = (const float*)d_in[12];
    const float* fb2   = (const float*)d_in[13];
    const float* sw3   = (const float*)d_in[14];
    const float* sg3   = (const float*)d_in[15];
    const float* sb3   = (const float*)d_in[16];
    const float* fw3   = (const float*)d_in[17];
    const float* fg3   = (const float*)d_in[18];
    const float* fb3   = (const float*)d_in[19];
    const float* ew    = (const float*)d_in[20];
    const float* eg    = (const float*)d_in[21];
    const float* ebv   = (const float*)d_in[22];
    const float* att_w = (const float*)d_in[23];
    const float* tn_w  = (const float*)d_in[24];
    const float* tn_wb = (const float*)d_in[25];
    const float* tn_b  = (const float*)d_in[26];
    const float* fc1_w = (const float*)d_in[27];
    const float* fc1_b = (const float*)d_in[28];
    const float* sc_w  = (const float*)d_in[29];
    const float* sc_b  = (const float*)d_in[30];
    float* out = (float*)d_out;

    unsigned* negp = (unsigned*)symaddr(g_neg);
    int*   idxp  = (int*)symaddr(g_idx);
    float* xxp   = symaddr(g_xx);
    float* x0p   = symaddr(g_x0);
    float* s0p   = symaddr(g_s0);
    float* h1p   = symaddr(g_h1);
    float* h2p   = symaddr(g_h2);
    float* h3p   = symaddr(g_h3);
    float* embp  = symaddr(g_emb);
    float* partp = symaddr(g_part);
    float* gcp   = symaddr(g_gc);
    float* ep    = symaddr(g_e);

    const int SM_C1 = (2*4*64    + 8*21*8  ) * 4 + 8*KNN*4;   // conv<3,4,64,8,128>
    const int SM_C2 = (2*64*64   + 8*21*68 ) * 4 + 8*KNN*4;   // conv<64,64,64,8,128>
    const int SM_C3 = (2*64*128  + 8*21*68 ) * 4 + 8*KNN*4;   // conv<64,64,128,8,256>
    const int SM_C4 = (2*128*64  + 8*21*132) * 4 + 8*KNN*4;   // conv<128,128,64,8,256>
    const int SM_EW = (256*128 + 4*256) * 4;

    cudaFuncSetAttribute(conv_kernel<64,64,64,8,128>,    cudaFuncAttributeMaxDynamicSharedMemorySize, SM_C2);
    cudaFuncSetAttribute(conv_kernel<64,64,128,8,256>,   cudaFuncAttributeMaxDynamicSharedMemorySize, SM_C3);
    cudaFuncSetAttribute(conv_kernel<128,128,64,8,256>,  cudaFuncAttributeMaxDynamicSharedMemorySize, SM_C4);
    cudaFuncSetAttribute(emb_kernel,                     cudaFuncAttributeMaxDynamicSharedMemorySize, SM_EW);

    transpose_kernel<<<(NB*131*NPT + 255) / 256, 256>>>(f1, f2, x0p, s0p);

    // ---- xyz chain: 3 -> 64 -> 64 -> 128 ----
    xx_kernel<4><<<NROW/256, 256>>>(x0p, xxp);
    dist_kernel<4><<<dim3(8,8,NB), 256>>>(x0p, xxp, negp);
    topk_kernel<<<NROW/8, 256>>>(negp, idxp);
    conv_kernel<3,4,64,8,128><<<NB*NPT/8, 128, SM_C1>>>(x0p, idxp, sw1, sg1, sb1, h1p);

    xx_kernel<64><<<NROW/256, 256>>>(h1p, xxp);
    dist_kernel<64><<<dim3(8,8,NB), 256>>>(h1p, xxp, negp);
    topk_kernel<<<NROW/8, 256>>>(negp, idxp);
    conv_kernel<64,64,64,8,128><<<NB*NPT/8, 128, SM_C2>>>(h1p, idxp, sw2, sg2, sb2, h2p);

    xx_kernel<64><<<NROW/256, 256>>>(h2p, xxp);
    dist_kernel<64><<<dim3(8,8,NB), 256>>>(h2p, xxp, negp);
    topk_kernel<<<NROW/8, 256>>>(negp, idxp);
    conv_kernel<64,64,128,8,256><<<NB*NPT/8, 256, SM_C3>>>(h2p, idxp, sw3, sg3, sb3, h3p);

    // ---- sem chain: 128 -> 64 -> 64 -> 128 ----
    xx_kernel<128><<<NROW/256, 256>>>(s0p, xxp);
    dist_kernel<128><<<dim3(8,8,NB), 256>>>(s0p, xxp, negp);
    topk_kernel<<<NROW/8, 256>>>(negp, idxp);
    conv_kernel<128,128,64,8,256><<<NB*NPT/8, 256, SM_C4>>>(s0p, idxp, fw1, fg1, fb1, h1p);

    xx_kernel<64><<<NROW/256, 256>>>(h1p, xxp);
    dist_kernel<64><<<dim3(8,8,NB), 256>>>(h1p, xxp, negp);
    topk_kernel<<<NROW/8, 256>>>(negp, idxp);
    conv_kernel<64,64,64,8,128><<<NB*NPT/8, 128, SM_C2>>>(h1p, idxp, fw2, fg2, fb2, h2p);

    xx_kernel<64><<<NROW/256, 256>>>(h2p, xxp);
    dist_kernel<64><<<dim3(8,8,NB), 256>>>(h2p, xxp, negp);
    topk_kernel<<<NROW/8, 256>>>(negp, idxp);
    conv_kernel<64,64,128,8,256><<<NB*NPT/8, 256, SM_C3>>>(h2p, idxp, fw3, fg3, fb3, s0p);  // s0p reused as S3

    // ---- fuse + attention (all 16 batches) ----
    emb_kernel<<<NROW/32, 128, SM_EW>>>(h3p, s0p, ew, eg, ebv, embp);

    float* att_out = out + 8;                       // att1 (b 0..7) then att2 (b 8..15), contiguous
    gcfused_kernel<<<NB, 1024>>>(embp, att_w, gcp);
    sc_kernel<<<NROW/4, 128>>>(embp, gcp, att_out);
    pool_part<<<dim3(NB, 8), 128>>>(embp, att_out, partp);
    pool_fin<<<NB, 128>>>(partp, ep);

    final_kernel<<<BB, 128>>>(ep, tn_w, tn_wb, tn_b, fc1_w, fc1_b, sc_w, sc_b, out);
}

// round 9
// speedup vs baseline: 1.4622x; 1.0197x over previous
#include <cuda_runtime.h>
#include <math.h>
#include <stdint.h>

#define BB   8
#define NB   16          // batches per graph-pair set
#define NB2  32          // both chains merged (xyz batches 0-15, sem 16-31)
#define NPT  1024
#define KNN  20
#define NROW (NB*NPT)    // 16384
#define NROW2 (NB2*NPT)  // 32768

// ------------------------------------------------------------------ packed fp32x2 helpers
__device__ __forceinline__ void ffma2(unsigned long long& d, unsigned long long a, unsigned long long b) {
    asm("fma.rn.f32x2 %0, %1, %2, %0;" : "+l"(d) : "l"(a), "l"(b));
}
__device__ __forceinline__ unsigned long long dup2(float x) {
    unsigned long long r;
    asm("mov.b64 %0, {%1, %1};" : "=l"(r) : "f"(x));
    return r;
}
__device__ __forceinline__ float2 unpk2(unsigned long long v) {
    float2 r;
    asm("mov.b64 {%0, %1}, %2;" : "=f"(r.x), "=f"(r.y) : "l"(v));
    return r;
}
__device__ __forceinline__ unsigned mapkey(float v) {
    unsigned u = __float_as_uint(v);
    return (u & 0x80000000u) ? ~u : (u | 0x80000000u);   // order-preserving; real keys > 0
}

// ------------------------------------------------------------------ scratch
__device__ unsigned g_neg[(size_t)NROW2*NPT];   // 128 MB mapped-key distance matrix
__device__ int   g_idx[NROW2*KNN];
__device__ float g_xx [NROW2];
__device__ float g_x0 [NROW*4];
__device__ float g_s0 [NROW*128];
__device__ float g_hA [NROW2*64];
__device__ float g_hB [NROW2*64];
__device__ float g_h3 [NROW2*128];     // layer-3 out: xyz half then sem half
__device__ float g_emb[NROW*128];
__device__ float g_part[NB*8*128];
__device__ float g_gc  [NB*128];
__device__ float g_e   [NB*128];

// ------------------------------------------------------------------ transpose both inputs (B,C,N) -> point-major
__global__ void transpose_kernel(const float* __restrict__ f1, const float* __restrict__ f2,
                                 float* __restrict__ x0, float* __restrict__ s0) {
    int j = blockIdx.x * blockDim.x + threadIdx.x;
    int total = NB * 131 * NPT;
    if (j >= total) return;
    int n = j % NPT;
    int c = (j / NPT) % 131;
    int b = j / (131 * NPT);
    const float* in = (b < BB) ? f1 : f2;
    float v = in[((long)(b & 7) * 131 + c) * NPT + n];
    if (c < 3) {
        x0[(b*NPT + n)*4 + c] = v;
        if (c == 0) x0[(b*NPT + n)*4 + 3] = 0.0f;
    } else {
        s0[((long)(b*NPT) + n)*128 + (c - 3)] = v;
    }
}

// ------------------------------------------------------------------ per-point squared norm (NR rows)
template <int CROW, int NR>
__global__ void xx_kernel(const float* __restrict__ X, float* __restrict__ xx) {
    int j = blockIdx.x * 256 + threadIdx.x;
    if (j >= NR) return;
    const float* r = X + (long)j * CROW;
    float a = 0.f;
    #pragma unroll
    for (int c = 0; c < CROW; c++) a += r[c] * r[c];
    xx[j] = a;
}

// ------------------------------------------------------------------ neg distance -> mapped u32 keys
// 128x128 tile, 256 threads, 8x8 register micro-tile, packed f32x2 FMA
template <int CROW>
__global__ __launch_bounds__(256, 1) void dist_kernel(const float* __restrict__ X,
                                                      const float* __restrict__ xx,
                                                      unsigned* __restrict__ neg) {
    constexpr int TC = (CROW < 16) ? CROW : 16;
    constexpr int LDW = 132;
    __shared__ float As[TC][LDW];
    __shared__ float Bs[TC][LDW];
    int b = blockIdx.z;
    int row0 = blockIdx.y * 128;
    int col0 = blockIdx.x * 128;
    int t = threadIdx.x;
    int tx = t & 15, ty = t >> 4;
    unsigned long long acc2[8][4];
    #pragma unroll
    for (int i = 0; i < 8; i++)
        #pragma unroll
        for (int j = 0; j < 4; j++) acc2[i][j] = 0ull;

    for (int c0 = 0; c0 < CROW; c0 += TC) {
        constexpr int NLD = (128 * TC) / 256;
        #pragma unroll
        for (int l = 0; l < NLD; l++) {
            int i = t + l * 256;
            int r = i / TC, c = i % TC;
            As[c][r] = X[((long)(b*NPT) + row0 + r) * CROW + c0 + c];
            Bs[c][r] = X[((long)(b*NPT) + col0 + r) * CROW + c0 + c];
        }
        __syncthreads();
        #pragma unroll
        for (int c = 0; c < TC; c++) {
            float4 a0 = *(const float4*)&As[c][ty*8];
            float4 a1 = *(const float4*)&As[c][ty*8+4];
            ulonglong2 b01 = *(const ulonglong2*)&Bs[c][tx*8];
            ulonglong2 b23 = *(const ulonglong2*)&Bs[c][tx*8+4];
            unsigned long long bp[4] = {b01.x, b01.y, b23.x, b23.y};
            unsigned long long ap[8];
            ap[0]=dup2(a0.x); ap[1]=dup2(a0.y); ap[2]=dup2(a0.z); ap[3]=dup2(a0.w);
            ap[4]=dup2(a1.x); ap[5]=dup2(a1.y); ap[6]=dup2(a1.z); ap[7]=dup2(a1.w);
            #pragma unroll
            for (int i = 0; i < 8; i++)
                #pragma unroll
                for (int j = 0; j < 4; j++) ffma2(acc2[i][j], ap[i], bp[j]);
        }
        __syncthreads();
    }
    float xr[8], xc[8];
    #pragma unroll
    for (int i = 0; i < 8; i++) {
        xr[i] = xx[b*NPT + row0 + ty*8 + i];
        xc[i] = xx[b*NPT + col0 + tx*8 + i];
    }
    #pragma unroll
    for (int i = 0; i < 8; i++) {
        long rbase = ((long)(b*NPT) + row0 + ty*8 + i) * NPT + col0 + tx*8;
        float2 p0 = unpk2(acc2[i][0]);
        float2 p1 = unpk2(acc2[i][1]);
        float2 p2 = unpk2(acc2[i][2]);
        float2 p3 = unpk2(acc2[i][3]);
        uint4 o0, o1;
        o0.x = mapkey(2.f*p0.x - xr[i] - xc[0]);
        o0.y = mapkey(2.f*p0.y - xr[i] - xc[1]);
        o0.z = mapkey(2.f*p1.x - xr[i] - xc[2]);
        o0.w = mapkey(2.f*p1.y - xr[i] - xc[3]);
        o1.x = mapkey(2.f*p2.x - xr[i] - xc[4]);
        o1.y = mapkey(2.f*p2.y - xr[i] - xc[5]);
        o1.z = mapkey(2.f*p3.x - xr[i] - xc[6]);
        o1.w = mapkey(2.f*p3.y - xr[i] - xc[7]);
        *(uint4*)&neg[rbase]     = o0;
        *(uint4*)&neg[rbase + 4] = o1;
    }
}

// ------------------------------------------------------------------ top-20: warp per row, REDUX argmax + per-lane top-4 cache
// neg holds order-preserving u32 keys (> 0). uint4 loads; gi = 128*g + 4*lane + q.
__global__ __launch_bounds__(256) void topk_kernel(const unsigned* __restrict__ neg, int* __restrict__ idxout) {
    int warp = threadIdx.x >> 5, lane = threadIdx.x & 31;
    long row = (long)blockIdx.x * 8 + warp;
    const unsigned* rp = neg + row * NPT;

    unsigned ck0=0,ck1=0,ck2=0,ck3=0;
    unsigned ci0=0,ci1=0,ci2=0,ci3=0;
    #pragma unroll
    for (int g = 0; g < 8; g++) {
        uint4 kv = *(const uint4*)&rp[g*128 + lane*4];
        unsigned kk[4] = {kv.x, kv.y, kv.z, kv.w};
        #pragma unroll
        for (int q = 0; q < 4; q++) {
            unsigned k = kk[q];
            unsigned gi = (unsigned)(g*128 + lane*4 + q);
            if (k > ck3) {
                if (k > ck0)      { ck3=ck2;ci3=ci2; ck2=ck1;ci2=ci1; ck1=ck0;ci1=ci0; ck0=k;ci0=gi; }
                else if (k > ck1) { ck3=ck2;ci3=ci2; ck2=ck1;ci2=ci1; ck1=k;ci1=gi; }
                else if (k > ck2) { ck3=ck2;ci3=ci2; ck2=k;ci2=gi; }
                else              { ck3=k;ci3=gi; }
            }
        }
    }
    unsigned removed = 0u;   // bit j = 4*g + q
    int navail = 4;
    for (int sel = 0; sel < KNN; sel++) {
        unsigned maxk = __reduce_max_sync(0xffffffffu, ck0);
        unsigned cand = (ck0 == maxk) ? ci0 : 0xffffffffu;
        unsigned widx = __reduce_min_sync(0xffffffffu, cand);
        if (lane == 0) idxout[row*KNN + sel] = (int)widx;
        if (ck0 == maxk && ci0 == widx) {        // unique owner
            int jw = (int)(((widx >> 7) << 2) | (widx & 3u));
            removed |= 1u << jw;
            ck0=ck1;ci0=ci1; ck1=ck2;ci1=ci2; ck2=ck3;ci2=ci3; ck3=0;ci3=0;
            if (--navail == 0) {                  // rare refill (lane needed 5+ wins)
                ck0=ck1=ck2=ck3=0; ci0=ci1=ci2=ci3=0;
                for (int g = 0; g < 8; g++) {
                    uint4 kv = *(const uint4*)&rp[g*128 + lane*4];
                    unsigned kk[4] = {kv.x, kv.y, kv.z, kv.w};
                    #pragma unroll
                    for (int q = 0; q < 4; q++) {
                        if ((removed >> (4*g + q)) & 1u) continue;
                        unsigned k = kk[q];
                        unsigned gi = (unsigned)(g*128 + lane*4 + q);
                        if (k > ck3) {
                            if (k > ck0)      { ck3=ck2;ci3=ci2; ck2=ck1;ci2=ci1; ck1=ck0;ci1=ci0; ck0=k;ci0=gi; }
                            else if (k > ck1) { ck3=ck2;ci3=ci2; ck2=ck1;ci2=ci1; ck1=k;ci1=gi; }
                            else if (k > ck2) { ck3=ck2;ci3=ci2; ck2=k;ci2=gi; }
                            else              { ck3=k;ci3=gi; }
                        }
                    }
                }
                navail = 4;
            }
        }
    }
}

// ------------------------------------------------------------------ fused gather + edge conv + BN + leaky + max_k
// dual weight sets: batches [0,NB) use set a, [NB,2NB) use set b
template <int CIN, int CROW, int COUT, int P, int THREADS>
__global__ __launch_bounds__(THREADS, 1)
void conv_kernel(const float* __restrict__ X, const int* __restrict__ idx,
                 const float* __restrict__ w_a, const float* __restrict__ w_b,
                 const float* __restrict__ gam_a, const float* __restrict__ gam_b,
                 const float* __restrict__ bet_a, const float* __restrict__ bet_b,
                 float* __restrict__ out) {
    constexpr int TPP = THREADS / P;
    constexpr int CPT = COUT / TPP;
    constexpr int NA  = CPT / 2;
    constexpr int CP  = CROW + 4;
    extern __shared__ float sm[];
    float* wt = sm;                          // [CROW][COUT]  (w1^T, zero-padded c>=CIN)
    float* wd = wt + CROW * COUT;            // [CROW][COUT]  (w2-w1)^T
    float* nb = wd + CROW * COUT;            // [P][21][CP]
    int* sidx = (int*)(nb + P * 21 * CP);    // [P][KNN]

    int t = threadIdx.x;
    int b  = blockIdx.x / (NPT / P);
    int n0 = (blockIdx.x % (NPT / P)) * P;
    const float* w   = (b < NB) ? w_a : w_b;
    const float* gam = (b < NB) ? gam_a : gam_b;
    const float* bet = (b < NB) ? bet_a : bet_b;

    for (int i = t; i < CROW * COUT; i += THREADS) {
        int c = i / COUT, o = i % COUT;
        float w1 = (c < CIN) ? w[o * (2*CIN) + c] : 0.f;
        float w2 = (c < CIN) ? w[o * (2*CIN) + CIN + c] : 0.f;
        wt[c * COUT + o] = w1;
        wd[c * COUT + o] = w2 - w1;
    }
    for (int i = t; i < P * KNN; i += THREADS)
        sidx[i] = idx[((long)(b*NPT) + n0) * KNN + i];
    __syncthreads();

    constexpr int V4 = CROW / 4;
    for (int i = t; i < P * 21 * V4; i += THREADS) {
        int c4 = i % V4;
        int vec = i / V4;
        int p = vec / 21, k = vec % 21;
        int m = (k < KNN) ? sidx[p*KNN + k] : (n0 + p);
        float4 v = *(const float4*)&X[((long)(b*NPT) + m) * CROW + 4*c4];
        *(float4*)&nb[(p*21 + k) * CP + 4*c4] = v;
    }
    __syncthreads();

    int p  = t / TPP;
    int o0 = (t % TPP) * CPT;
    unsigned long long s2[KNN][NA];
    unsigned long long u2[NA];
    #pragma unroll
    for (int k = 0; k < KNN; k++)
        #pragma unroll
        for (int a = 0; a < NA; a++) s2[k][a] = 0ull;
    #pragma unroll
    for (int a = 0; a < NA; a++) u2[a] = 0ull;

    const float* nbp = nb + p * 21 * CP;
    #pragma unroll 1
    for (int c4i = 0; c4i < CROW/4; c4i++) {
        int c = 4 * c4i;
        unsigned long long w1p[4][NA], wdp[4][NA];
        #pragma unroll
        for (int q = 0; q < 4; q++)
            #pragma unroll
            for (int a = 0; a < NA; a++) {
                w1p[q][a] = *(const unsigned long long*)&wt[(c+q) * COUT + o0 + 2*a];
                wdp[q][a] = *(const unsigned long long*)&wd[(c+q) * COUT + o0 + 2*a];
            }
        float4 ct4 = *(const float4*)&nbp[20 * CP + c];
        unsigned long long ctd[4] = {dup2(ct4.x), dup2(ct4.y), dup2(ct4.z), dup2(ct4.w)};
        #pragma unroll
        for (int q = 0; q < 4; q++)
            #pragma unroll
            for (int a = 0; a < NA; a++) ffma2(u2[a], wdp[q][a], ctd[q]);
        #pragma unroll
        for (int k = 0; k < KNN; k++) {
            float4 nv = *(const float4*)&nbp[k * CP + c];
            unsigned long long nd[4] = {dup2(nv.x), dup2(nv.y), dup2(nv.z), dup2(nv.w)};
            #pragma unroll
            for (int q = 0; q < 4; q++)
                #pragma unroll
                for (int a = 0; a < NA; a++) ffma2(s2[k][a], w1p[q][a], nd[q]);
        }
    }
    float inv = rsqrtf(1.0f + 1e-5f);
    float res[CPT];
    #pragma unroll
    for (int a = 0; a < NA; a++) {
        float2 m0 = unpk2(s2[0][a]);
        float2 mx = m0, mn = m0;
        #pragma unroll
        for (int k = 1; k < KNN; k++) {
            float2 v = unpk2(s2[k][a]);
            mx.x = fmaxf(mx.x, v.x); mx.y = fmaxf(mx.y, v.y);
            mn.x = fminf(mn.x, v.x); mn.y = fminf(mn.y, v.y);
        }
        float2 uv = unpk2(u2[a]);
        float g0 = gam[o0 + 2*a], g1 = gam[o0 + 2*a + 1];
        float b0 = bet[o0 + 2*a], b1 = bet[o0 + 2*a + 1];
        { float aa = g0*inv; float base = ((aa>=0.f)?mx.x:mn.x) + uv.x; float v = aa*base + b0; res[2*a]   = v>=0.f?v:0.2f*v; }
        { float aa = g1*inv; float base = ((aa>=0.f)?mx.y:mn.y) + uv.y; float v = aa*base + b1; res[2*a+1] = v>=0.f?v:0.2f*v; }
    }
    int n = n0 + p;
    float* op = &out[((long)(b*NPT) + n) * COUT + o0];
    if constexpr (NA == 2) {
        *(float4*)op = make_float4(res[0], res[1], res[2], res[3]);
    } else {
        *(float2*)op = make_float2(res[0], res[1]);
    }
}

// ------------------------------------------------------------------ ew conv on concat(H3,S3) -> emb (packed FMA)
__global__ __launch_bounds__(128)
void emb_kernel(const float* __restrict__ H3, const float* __restrict__ S3,
                const float* __restrict__ ew, const float* __restrict__ eg,
                const float* __restrict__ eb, float* __restrict__ emb) {
    extern __shared__ float sm[];
    float* wts  = sm;                 // [256][128]
    float* rows = wts + 256 * 128;    // [4][256]
    int t = threadIdx.x;
    for (int i = t; i < 256 * 128; i += 128) {
        int c = i / 128, o = i % 128;
        wts[c * 128 + o] = ew[o * 256 + c];
    }
    const int NITER = 8;
    int base = blockIdx.x * (4 * NITER);
    int pl = t / 32;
    int o4 = (t % 32) * 4;
    float inv = rsqrtf(1.0f + 1e-5f);
    for (int it = 0; it < NITER; it++) {
        __syncthreads();
        int p0 = base + it * 4;
        for (int i = t; i < 4 * 256; i += 128) {
            int pp = i / 256, c = i % 256;
            long pt = p0 + pp;
            rows[pp * 256 + c] = (c < 128) ? H3[pt * 128 + c] : S3[pt * 128 + c - 128];
        }
        __syncthreads();
        unsigned long long acc2[2] = {0ull, 0ull};
        for (int c = 0; c < 256; c++) {
            ulonglong2 wp = *(const ulonglong2*)&wts[c * 128 + o4];
            unsigned long long xd = dup2(rows[pl * 256 + c]);
            ffma2(acc2[0], wp.x, xd);
            ffma2(acc2[1], wp.y, xd);
        }
        float2 axy = unpk2(acc2[0]);
        float2 azw = unpk2(acc2[1]);
        float4 gmv = *(const float4*)&eg[o4];
        float4 btv = *(const float4*)&eb[o4];
        float4 r;
        { float v = gmv.x*inv*axy.x + btv.x; r.x = v>=0.f?v:0.2f*v; }
        { float v = gmv.y*inv*axy.y + btv.y; r.y = v>=0.f?v:0.2f*v; }
        { float v = gmv.z*inv*azw.x + btv.z; r.z = v>=0.f?v:0.2f*v; }
        { float v = gmv.w*inv*azw.y + btv.w; r.w = v>=0.f?v:0.2f*v; }
        long pt = p0 + pl;
        *(float4*)&emb[pt * 128 + o4] = r;
    }
}

// ------------------------------------------------------------------ attention pieces
__global__ void gcfused_kernel(const float* __restrict__ emb, const float* __restrict__ att_w,
                               float* __restrict__ gc) {
    __shared__ float part[8][128];
    __shared__ float es[128];
    int b = blockIdx.x, t = threadIdx.x;      // 1024 threads
    int seg = t >> 7, f = t & 127;
    const float* p = emb + ((long)(b*NPT) + seg*128) * 128 + f;
    float a = 0.f;
    #pragma unroll 4
    for (int n = 0; n < 128; n++) a += p[n * 128];
    part[seg][f] = a;
    __syncthreads();
    if (t < 128) {
        float s = 0.f;
        #pragma unroll
        for (int s8 = 0; s8 < 8; s8++) s += part[s8][t];
        es[t] = s;
    }
    __syncthreads();
    if (t < 128) {
        float gv = 0.f;
        for (int f2 = 0; f2 < 128; f2++) gv += es[f2] * att_w[f2 * 128 + t];
        gc[b * 128 + t] = tanhf(gv * (1.0f / NPT));
    }
}

__global__ void sc_kernel(const float* __restrict__ emb, const float* __restrict__ gc,
                          float* __restrict__ att) {
    int warp = threadIdx.x >> 5, lane = threadIdx.x & 31;
    int pid = blockIdx.x * 4 + warp;
    int b = pid >> 10;
    float a = 0.f;
    #pragma unroll
    for (int j = 0; j < 4; j++) {
        int f = lane + 32 * j;
        a += emb[(long)pid * 128 + f] * gc[b * 128 + f];
    }
    #pragma unroll
    for (int off = 16; off; off >>= 1) a += __shfl_down_sync(0xffffffffu, a, off);
    if (lane == 0) att[pid] = 1.0f / (1.0f + expf(-a));
}

__global__ void pool_part(const float* __restrict__ emb, const float* __restrict__ att,
                          float* __restrict__ part) {
    int b = blockIdx.x, seg = blockIdx.y, f = threadIdx.x;
    const float* p = emb + ((long)(b*NPT) + seg*128) * 128 + f;
    const float* aw = att + b*NPT + seg*128;
    float a = 0.f;
    #pragma unroll 4
    for (int n = 0; n < 128; n++) a += p[n * 128] * aw[n];
    part[(b*8 + seg) * 128 + f] = a;
}

__global__ void pool_fin(const float* __restrict__ part, float* __restrict__ e) {
    int b = blockIdx.x, t = threadIdx.x;
    float a = 0.f;
    #pragma unroll
    for (int s = 0; s < 8; s++) a += part[(b*8 + s) * 128 + t];
    e[b * 128 + t] = a;
}

// ------------------------------------------------------------------ final scoring
__global__ void final_kernel(const float* __restrict__ e, const float* __restrict__ tn_w,
                             const float* __restrict__ tn_wb, const float* __restrict__ tn_bias,
                             const float* __restrict__ fc1_w, const float* __restrict__ fc1_b,
                             const float* __restrict__ sc_w, const float* __restrict__ sc_b,
                             float* __restrict__ out) {
    __shared__ float e1s[128], e2s[128], red[128], ts[16], hs[16];
    int b = blockIdx.x, tid = threadIdx.x;
    e1s[tid] = e[b * 128 + tid];
    e2s[tid] = e[(b + 8) * 128 + tid];
    __syncthreads();
    for (int tt = 0; tt < 16; tt++) {
        float inner = 0.f;
        const float* wrow = tn_w + (long)tid * 128 * 16 + tt;
        for (int gI = 0; gI < 128; gI++) inner += wrow[gI * 16] * e2s[gI];
        red[tid] = e1s[tid] * inner;
        __syncthreads();
        for (int s2 = 64; s2; s2 >>= 1) {
            if (tid < s2) red[tid] += red[tid + s2];
            __syncthreads();
        }
        if (tid == 0) ts[tt] = red[0];
        __syncthreads();
    }
    if (tid < 16) {
        float blk = 0.f;
        for (int c = 0; c < 128; c++) blk += tn_wb[tid * 256 + c] * e1s[c];
        for (int c = 0; c < 128; c++) blk += tn_wb[tid * 256 + 128 + c] * e2s[c];
        float v = ts[tid] + blk + tn_bias[tid];
        ts[tid] = v > 0.f ? v : 0.f;
    }
    __syncthreads();
    if (tid < 16) {
        float h = fc1_b[tid];
        for (int u2 = 0; u2 < 16; u2++) h += fc1_w[tid * 16 + u2] * ts[u2];
        hs[tid] = h > 0.f ? h : 0.f;
    }
    __syncthreads();
    if (tid == 0) {
        float z = sc_b[0];
        for (int u2 = 0; u2 < 16; u2++) z += sc_w[u2] * hs[u2];
        out[b] = 1.0f / (1.0f + expf(-z));
    }
}

// ------------------------------------------------------------------ host
template <typename T>
static float* symaddr(T& sym_) {
    void* p = nullptr;
    cudaGetSymbolAddress(&p, sym_);
    return (float*)p;
}

extern "C" void kernel_launch(void* const* d_in, const int* in_sizes, int n_in,
                              void* d_out, int out_size) {
    (void)in_sizes; (void)n_in; (void)out_size;
    const float* f1    = (const float*)d_in[0];
    const float* f2    = (const float*)d_in[1];
    const float* sw1   = (const float*)d_in[2];
    const float* sg1   = (const float*)d_in[3];
    const float* sb1   = (const float*)d_in[4];
    const float* fw1   = (const float*)d_in[5];
    const float* fg1   = (const float*)d_in[6];
    const float* fb1   = (const float*)d_in[7];
    const float* sw2   = (const float*)d_in[8];
    const float* sg2   = (const float*)d_in[9];
    const float* sb2   = (const float*)d_in[10];
    const float* fw2   = (const float*)d_in[11];
    const float* fg2   = (const float*)d_in[12];
    const float* fb2   = (const float*)d_in[13];
    const float* sw3   = (const float*)d_in[14];
    const float* sg3   = (const float*)d_in[15];
    const float* sb3   = (const float*)d_in[16];
    const float* fw3   = (const float*)d_in[17];
    const float* fg3   = (const float*)d_in[18];
    const float* fb3   = (const float*)d_in[19];
    const float* ew    = (const float*)d_in[20];
    const float* eg    = (const float*)d_in[21];
    const float* ebv   = (const float*)d_in[22];
    const float* att_w = (const float*)d_in[23];
    const float* tn_w  = (const float*)d_in[24];
    const float* tn_wb = (const float*)d_in[25];
    const float* tn_b  = (const float*)d_in[26];
    const float* fc1_w = (const float*)d_in[27];
    const float* fc1_b = (const float*)d_in[28];
    const float* sc_w  = (const float*)d_in[29];
    const float* sc_b  = (const float*)d_in[30];
    float* out = (float*)d_out;

    unsigned* negp = (unsigned*)symaddr(g_neg);
    int*   idxp  = (int*)symaddr(g_idx);
    float* xxp   = symaddr(g_xx);
    float* x0p   = symaddr(g_x0);
    float* s0p   = symaddr(g_s0);
    float* hAp   = symaddr(g_hA);
    float* hBp   = symaddr(g_hB);
    float* h3p   = symaddr(g_h3);
    float* embp  = symaddr(g_emb);
    float* partp = symaddr(g_part);
    float* gcp   = symaddr(g_gc);
    float* ep    = symaddr(g_e);

    const int SM_C1 = (2*4*64    + 8*21*8  ) * 4 + 8*KNN*4;   // conv<3,4,64,8,128>
    const int SM_C2 = (2*64*64   + 8*21*68 ) * 4 + 8*KNN*4;   // conv<64,64,64,8,128>
    const int SM_C3 = (2*64*128  + 8*21*68 ) * 4 + 8*KNN*4;   // conv<64,64,128,8,256>
    const int SM_C4 = (2*128*64  + 8*21*132) * 4 + 8*KNN*4;   // conv<128,128,64,8,256>
    const int SM_EW = (256*128 + 4*256) * 4;

    cudaFuncSetAttribute(conv_kernel<64,64,64,8,128>,    cudaFuncAttributeMaxDynamicSharedMemorySize, SM_C2);
    cudaFuncSetAttribute(conv_kernel<64,64,128,8,256>,   cudaFuncAttributeMaxDynamicSharedMemorySize, SM_C3);
    cudaFuncSetAttribute(conv_kernel<128,128,64,8,256>,  cudaFuncAttributeMaxDynamicSharedMemorySize, SM_C4);
    cudaFuncSetAttribute(emb_kernel,                     cudaFuncAttributeMaxDynamicSharedMemorySize, SM_EW);

    transpose_kernel<<<(NB*131*NPT + 255) / 256, 256>>>(f1, f2, x0p, s0p);

    // ---- layer 1: xyz (C=4) and sem (C=128) dists share one key buffer + one topk ----
    xx_kernel<4,NROW><<<NROW/256, 256>>>(x0p, xxp);
    xx_kernel<128,NROW><<<NROW/256, 256>>>(s0p, xxp + NROW);
    dist_kernel<4><<<dim3(8,8,NB), 256>>>(x0p, xxp, negp);
    dist_kernel<128><<<dim3(8,8,NB), 256>>>(s0p, xxp + NROW, negp + (size_t)NROW*NPT);
    topk_kernel<<<NROW2/8, 256>>>(negp, idxp);
    conv_kernel<3,4,64,8,128><<<NB*NPT/8, 128, SM_C1>>>(x0p, idxp, sw1, sw1, sg1, sg1, sb1, sb1, hAp);
    conv_kernel<128,128,64,8,256><<<NB*NPT/8, 256, SM_C4>>>(s0p, idxp + NROW*KNN, fw1, fw1, fg1, fg1, fb1, fb1, hAp + NROW*64);

    // ---- layer 2 (both chains merged, 64 -> 64) ----
    xx_kernel<64,NROW2><<<NROW2/256, 256>>>(hAp, xxp);
    dist_kernel<64><<<dim3(8,8,NB2), 256>>>(hAp, xxp, negp);
    topk_kernel<<<NROW2/8, 256>>>(negp, idxp);
    conv_kernel<64,64,64,8,128><<<NB2*NPT/8, 128, SM_C2>>>(hAp, idxp, sw2, fw2, sg2, fg2, sb2, fb2, hBp);

    // ---- layer 3 (both chains merged, 64 -> 128) ----
    xx_kernel<64,NROW2><<<NROW2/256, 256>>>(hBp, xxp);
    dist_kernel<64><<<dim3(8,8,NB2), 256>>>(hBp, xxp, negp);
    topk_kernel<<<NROW2/8, 256>>>(negp, idxp);
    conv_kernel<64,64,128,8,256><<<NB2*NPT/8, 256, SM_C3>>>(hBp, idxp, sw3, fw3, sg3, fg3, sb3, fb3, h3p);

    // ---- fuse + attention (all 16 batches) ----
    emb_kernel<<<NROW/32, 128, SM_EW>>>(h3p, h3p + NROW*128, ew, eg, ebv, embp);

    float* att_out = out + 8;                       // att1 (b 0..7) then att2 (b 8..15), contiguous
    gcfused_kernel<<<NB, 1024>>>(embp, att_w, gcp);
    sc_kernel<<<NROW/4, 128>>>(embp, gcp, att_out);
    pool_part<<<dim3(NB, 8), 128>>>(embp, att_out, partp);
    pool_fin<<<NB, 128>>>(partp, ep);

    final_kernel<<<BB, 128>>>(ep, tn_w, tn_wb, tn_b, fc1_w, fc1_b, sc_w, sc_b, out);
}

// round 10
// speedup vs baseline: 1.7814x; 1.2183x over previous
#include <cuda_runtime.h>
#include <math.h>
#include <stdint.h>

#define BB   8
#define NB   16          // batches per graph-pair set
#define NB2  32          // both chains merged (xyz batches 0-15, sem 16-31)
#define NPT  1024
#define KNN  20
#define NROW (NB*NPT)    // 16384
#define NROW2 (NB2*NPT)  // 32768

// ------------------------------------------------------------------ packed fp32x2 helpers
__device__ __forceinline__ void ffma2(unsigned long long& d, unsigned long long a, unsigned long long b) {
    asm("fma.rn.f32x2 %0, %1, %2, %0;" : "+l"(d) : "l"(a), "l"(b));
}
__device__ __forceinline__ unsigned long long dup2(float x) {
    unsigned long long r;
    asm("mov.b64 %0, {%1, %1};" : "=l"(r) : "f"(x));
    return r;
}
__device__ __forceinline__ float2 unpk2(unsigned long long v) {
    float2 r;
    asm("mov.b64 {%0, %1}, %2;" : "=f"(r.x), "=f"(r.y) : "l"(v));
    return r;
}
__device__ __forceinline__ unsigned mapkey(float v) {
    unsigned u = __float_as_uint(v);
    return (u & 0x80000000u) ? ~u : (u | 0x80000000u);   // order-preserving; real keys > 0
}

// ------------------------------------------------------------------ scratch
__device__ unsigned g_neg[(size_t)NROW2*NPT];   // 128 MB mapped-key distance matrix
__device__ int   g_idx[NROW2*KNN];
__device__ float g_xx [NROW2];
__device__ float g_x0 [NROW*4];
__device__ float g_s0 [NROW*128];
__device__ float g_hA [NROW2*64];
__device__ float g_hB [NROW2*64];
__device__ float g_h3 [NROW2*128];     // layer-3 out: xyz half then sem half
__device__ float g_emb[NROW*128];
__device__ float g_part[NB*8*128];
__device__ float g_gc  [NB*128];
__device__ float g_e   [NB*128];

// ------------------------------------------------------------------ transpose both inputs (B,C,N) -> point-major
__global__ void transpose_kernel(const float* __restrict__ f1, const float* __restrict__ f2,
                                 float* __restrict__ x0, float* __restrict__ s0) {
    int j = blockIdx.x * blockDim.x + threadIdx.x;
    int total = NB * 131 * NPT;
    if (j >= total) return;
    int n = j % NPT;
    int c = (j / NPT) % 131;
    int b = j / (131 * NPT);
    const float* in = (b < BB) ? f1 : f2;
    float v = in[((long)(b & 7) * 131 + c) * NPT + n];
    if (c < 3) {
        x0[(b*NPT + n)*4 + c] = v;
        if (c == 0) x0[(b*NPT + n)*4 + 3] = 0.0f;
    } else {
        s0[((long)(b*NPT) + n)*128 + (c - 3)] = v;
    }
}

// ------------------------------------------------------------------ per-point squared norm (NR rows)
template <int CROW, int NR>
__global__ void xx_kernel(const float* __restrict__ X, float* __restrict__ xx) {
    int j = blockIdx.x * 256 + threadIdx.x;
    if (j >= NR) return;
    const float* r = X + (long)j * CROW;
    float a = 0.f;
    #pragma unroll
    for (int c = 0; c < CROW; c++) a += r[c] * r[c];
    xx[j] = a;
}

// ------------------------------------------------------------------ neg distance -> mapped u32 keys
// 128x128 tile, 256 threads, 8x8 register micro-tile, packed f32x2 FMA
template <int CROW>
__global__ __launch_bounds__(256, 1) void dist_kernel(const float* __restrict__ X,
                                                      const float* __restrict__ xx,
                                                      unsigned* __restrict__ neg) {
    constexpr int TC = (CROW < 16) ? CROW : 16;
    constexpr int LDW = 132;
    __shared__ float As[TC][LDW];
    __shared__ float Bs[TC][LDW];
    int b = blockIdx.z;
    int row0 = blockIdx.y * 128;
    int col0 = blockIdx.x * 128;
    int t = threadIdx.x;
    int tx = t & 15, ty = t >> 4;
    unsigned long long acc2[8][4];
    #pragma unroll
    for (int i = 0; i < 8; i++)
        #pragma unroll
        for (int j = 0; j < 4; j++) acc2[i][j] = 0ull;

    for (int c0 = 0; c0 < CROW; c0 += TC) {
        constexpr int NLD = (128 * TC) / 256;
        #pragma unroll
        for (int l = 0; l < NLD; l++) {
            int i = t + l * 256;
            int r = i / TC, c = i % TC;
            As[c][r] = X[((long)(b*NPT) + row0 + r) * CROW + c0 + c];
            Bs[c][r] = X[((long)(b*NPT) + col0 + r) * CROW + c0 + c];
        }
        __syncthreads();
        #pragma unroll
        for (int c = 0; c < TC; c++) {
            float4 a0 = *(const float4*)&As[c][ty*8];
            float4 a1 = *(const float4*)&As[c][ty*8+4];
            ulonglong2 b01 = *(const ulonglong2*)&Bs[c][tx*8];
            ulonglong2 b23 = *(const ulonglong2*)&Bs[c][tx*8+4];
            unsigned long long bp[4] = {b01.x, b01.y, b23.x, b23.y};
            unsigned long long ap[8];
            ap[0]=dup2(a0.x); ap[1]=dup2(a0.y); ap[2]=dup2(a0.z); ap[3]=dup2(a0.w);
            ap[4]=dup2(a1.x); ap[5]=dup2(a1.y); ap[6]=dup2(a1.z); ap[7]=dup2(a1.w);
            #pragma unroll
            for (int i = 0; i < 8; i++)
                #pragma unroll
                for (int j = 0; j < 4; j++) ffma2(acc2[i][j], ap[i], bp[j]);
        }
        __syncthreads();
    }
    float xr[8], xc[8];
    #pragma unroll
    for (int i = 0; i < 8; i++) {
        xr[i] = xx[b*NPT + row0 + ty*8 + i];
        xc[i] = xx[b*NPT + col0 + tx*8 + i];
    }
    #pragma unroll
    for (int i = 0; i < 8; i++) {
        long rbase = ((long)(b*NPT) + row0 + ty*8 + i) * NPT + col0 + tx*8;
        float2 p0 = unpk2(acc2[i][0]);
        float2 p1 = unpk2(acc2[i][1]);
        float2 p2 = unpk2(acc2[i][2]);
        float2 p3 = unpk2(acc2[i][3]);
        uint4 o0, o1;
        o0.x = mapkey(2.f*p0.x - xr[i] - xc[0]);
        o0.y = mapkey(2.f*p0.y - xr[i] - xc[1]);
        o0.z = mapkey(2.f*p1.x - xr[i] - xc[2]);
        o0.w = mapkey(2.f*p1.y - xr[i] - xc[3]);
        o1.x = mapkey(2.f*p2.x - xr[i] - xc[4]);
        o1.y = mapkey(2.f*p2.y - xr[i] - xc[5]);
        o1.z = mapkey(2.f*p3.x - xr[i] - xc[6]);
        o1.w = mapkey(2.f*p3.y - xr[i] - xc[7]);
        *(uint4*)&neg[rbase]     = o0;
        *(uint4*)&neg[rbase + 4] = o1;
    }
}

// ------------------------------------------------------------------ top-20: warp per row, REDUX argmax + per-lane top-4 cache
__global__ __launch_bounds__(256) void topk_kernel(const unsigned* __restrict__ neg, int* __restrict__ idxout) {
    int warp = threadIdx.x >> 5, lane = threadIdx.x & 31;
    long row = (long)blockIdx.x * 8 + warp;
    const unsigned* rp = neg + row * NPT;

    unsigned ck0=0,ck1=0,ck2=0,ck3=0;
    unsigned ci0=0,ci1=0,ci2=0,ci3=0;
    #pragma unroll
    for (int g = 0; g < 8; g++) {
        uint4 kv = *(const uint4*)&rp[g*128 + lane*4];
        unsigned kk[4] = {kv.x, kv.y, kv.z, kv.w};
        #pragma unroll
        for (int q = 0; q < 4; q++) {
            unsigned k = kk[q];
            unsigned gi = (unsigned)(g*128 + lane*4 + q);
            if (k > ck3) {
                if (k > ck0)      { ck3=ck2;ci3=ci2; ck2=ck1;ci2=ci1; ck1=ck0;ci1=ci0; ck0=k;ci0=gi; }
                else if (k > ck1) { ck3=ck2;ci3=ci2; ck2=ck1;ci2=ci1; ck1=k;ci1=gi; }
                else if (k > ck2) { ck3=ck2;ci3=ci2; ck2=k;ci2=gi; }
                else              { ck3=k;ci3=gi; }
            }
        }
    }
    unsigned removed = 0u;   // bit j = 4*g + q
    int navail = 4;
    for (int sel = 0; sel < KNN; sel++) {
        unsigned maxk = __reduce_max_sync(0xffffffffu, ck0);
        unsigned cand = (ck0 == maxk) ? ci0 : 0xffffffffu;
        unsigned widx = __reduce_min_sync(0xffffffffu, cand);
        if (lane == 0) idxout[row*KNN + sel] = (int)widx;
        if (ck0 == maxk && ci0 == widx) {        // unique owner
            int jw = (int)(((widx >> 7) << 2) | (widx & 3u));
            removed |= 1u << jw;
            ck0=ck1;ci0=ci1; ck1=ck2;ci1=ci2; ck2=ck3;ci2=ci3; ck3=0;ci3=0;
            if (--navail == 0) {                  // rare refill (lane needed 5+ wins)
                ck0=ck1=ck2=ck3=0; ci0=ci1=ci2=ci3=0;
                for (int g = 0; g < 8; g++) {
                    uint4 kv = *(const uint4*)&rp[g*128 + lane*4];
                    unsigned kk[4] = {kv.x, kv.y, kv.z, kv.w};
                    #pragma unroll
                    for (int q = 0; q < 4; q++) {
                        if ((removed >> (4*g + q)) & 1u) continue;
                        unsigned k = kk[q];
                        unsigned gi = (unsigned)(g*128 + lane*4 + q);
                        if (k > ck3) {
                            if (k > ck0)      { ck3=ck2;ci3=ci2; ck2=ck1;ci2=ci1; ck1=ck0;ci1=ci0; ck0=k;ci0=gi; }
                            else if (k > ck1) { ck3=ck2;ci3=ci2; ck2=ck1;ci2=ci1; ck1=k;ci1=gi; }
                            else if (k > ck2) { ck3=ck2;ci3=ci2; ck2=k;ci2=gi; }
                            else              { ck3=k;ci3=gi; }
                        }
                    }
                }
                navail = 4;
            }
        }
    }
}

// ------------------------------------------------------------------ fused gather + edge conv + BN + leaky + max_k  (v4: c-paired FFMA2)
// Accumulators packed over channel parity: s[k] = (sum over even c, sum over odd c).
// Weights transposed in smem [COUT][CROW+2]; nb kept [p][21][CPH+4] (broadcast LDS.64 c-pairs).
// Each thread owns outputs o0 = t%TPP and o1 = o0 + COUT/2. NPH channel phases (nb reloaded per phase).
template <int CIN, int CROW, int COUT, int P, int THREADS, int NPH>
__global__ __launch_bounds__(THREADS, 1)
void conv_kernel(const float* __restrict__ X, const int* __restrict__ idx,
                 const float* __restrict__ w_a, const float* __restrict__ w_b,
                 const float* __restrict__ gam_a, const float* __restrict__ gam_b,
                 const float* __restrict__ bet_a, const float* __restrict__ bet_b,
                 float* __restrict__ out) {
    constexpr int TPP = THREADS / P;          // threads per point = COUT/2
    static_assert(TPP == COUT / 2, "CPT must be 2");
    constexpr int CPH = CROW / NPH;           // channels per phase
    constexpr int WST = CROW + 2;             // transposed weight row stride (even -> aligned LDS.64)
    constexpr int CP  = CPH + 4;              // nb row stride
    extern __shared__ float sm[];
    float* w1T = sm;                          // [COUT][WST]
    float* wdT = w1T + COUT * WST;            // [COUT][WST]
    float* nb  = wdT + COUT * WST;            // [P][21][CP]
    int* sidx  = (int*)(nb + P * 21 * CP);    // [P][KNN]

    int t = threadIdx.x;
    int b  = blockIdx.x / (NPT / P);
    int n0 = (blockIdx.x % (NPT / P)) * P;
    const float* w   = (b < NB) ? w_a : w_b;
    const float* gam = (b < NB) ? gam_a : gam_b;
    const float* bet = (b < NB) ? bet_a : bet_b;

    for (int i = t; i < COUT * CROW; i += THREADS) {
        int o = i / CROW, c = i % CROW;
        float w1 = (c < CIN) ? w[o * (2*CIN) + c] : 0.f;
        float w2 = (c < CIN) ? w[o * (2*CIN) + CIN + c] : 0.f;
        w1T[o * WST + c] = w1;
        wdT[o * WST + c] = w2 - w1;
    }
    for (int i = t; i < P * KNN; i += THREADS)
        sidx[i] = idx[((long)(b*NPT) + n0) * KNN + i];
    __syncthreads();

    int p  = t / TPP;
    int o0 = t % TPP;
    int o1 = o0 + COUT / 2;
    unsigned long long s0[KNN], s1[KNN];
    unsigned long long u0 = 0ull, u1 = 0ull;
    #pragma unroll
    for (int k = 0; k < KNN; k++) { s0[k] = 0ull; s1[k] = 0ull; }

    const float* nbp = nb + p * 21 * CP;
    constexpr int V4 = CPH / 4;
    for (int ph = 0; ph < NPH; ph++) {
        if (ph > 0) __syncthreads();          // prior phase compute done before overwrite
        for (int i = t; i < P * 21 * V4; i += THREADS) {
            int c4 = i % V4;
            int vec = i / V4;
            int pp = vec / 21, k = vec % 21;
            int m = (k < KNN) ? sidx[pp*KNN + k] : (n0 + pp);
            float4 v = *(const float4*)&X[((long)(b*NPT) + m) * CROW + ph*CPH + 4*c4];
            *(float4*)&nb[(pp*21 + k) * CP + 4*c4] = v;
        }
        __syncthreads();

        #pragma unroll 1
        for (int c2 = 0; c2 < CPH/2; c2++) {
            int cl = 2 * c2;
            int cg = ph * CPH + cl;
            unsigned long long w1p0 = *(const unsigned long long*)&w1T[o0 * WST + cg];
            unsigned long long w1p1 = *(const unsigned long long*)&w1T[o1 * WST + cg];
            unsigned long long wdp0 = *(const unsigned long long*)&wdT[o0 * WST + cg];
            unsigned long long wdp1 = *(const unsigned long long*)&wdT[o1 * WST + cg];
            unsigned long long ctr = *(const unsigned long long*)&nbp[20 * CP + cl];
            ffma2(u0, wdp0, ctr);
            ffma2(u1, wdp1, ctr);
            #pragma unroll
            for (int k = 0; k < KNN; k++) {
                unsigned long long nbk = *(const unsigned long long*)&nbp[k * CP + cl];
                ffma2(s0[k], w1p0, nbk);
                ffma2(s1[k], w1p1, nbk);
            }
        }
    }

    float inv = rsqrtf(1.0f + 1e-5f);
    int n = n0 + p;
    float* op = &out[((long)(b*NPT) + n) * COUT];
    // output o0
    {
        float2 h = unpk2(s0[0]);
        float v0 = h.x + h.y;
        float mx = v0, mn = v0;
        #pragma unroll
        for (int k = 1; k < KNN; k++) {
            float2 hk = unpk2(s0[k]);
            float vk = hk.x + hk.y;
            mx = fmaxf(mx, vk); mn = fminf(mn, vk);
        }
        float2 up = unpk2(u0);
        float uu = up.x + up.y;
        float g = gam[o0], bt = bet[o0];
        float aa = g * inv;
        float base = ((aa >= 0.f) ? mx : mn) + uu;
        float v = aa * base + bt;
        op[o0] = v >= 0.f ? v : 0.2f * v;
    }
    // output o1
    {
        float2 h = unpk2(s1[0]);
        float v0 = h.x + h.y;
        float mx = v0, mn = v0;
        #pragma unroll
        for (int k = 1; k < KNN; k++) {
            float2 hk = unpk2(s1[k]);
            float vk = hk.x + hk.y;
            mx = fmaxf(mx, vk); mn = fminf(mn, vk);
        }
        float2 up = unpk2(u1);
        float uu = up.x + up.y;
        float g = gam[o1], bt = bet[o1];
        float aa = g * inv;
        float base = ((aa >= 0.f) ? mx : mn) + uu;
        float v = aa * base + bt;
        op[o1] = v >= 0.f ? v : 0.2f * v;
    }
}

// ------------------------------------------------------------------ ew conv on concat(H3,S3) -> emb (packed FMA)
__global__ __launch_bounds__(128)
void emb_kernel(const float* __restrict__ H3, const float* __restrict__ S3,
                const float* __restrict__ ew, const float* __restrict__ eg,
                const float* __restrict__ eb, float* __restrict__ emb) {
    extern __shared__ float sm[];
    float* wts  = sm;                 // [256][128]
    float* rows = wts + 256 * 128;    // [4][256]
    int t = threadIdx.x;
    for (int i = t; i < 256 * 128; i += 128) {
        int c = i / 128, o = i % 128;
        wts[c * 128 + o] = ew[o * 256 + c];
    }
    const int NITER = 8;
    int base = blockIdx.x * (4 * NITER);
    int pl = t / 32;
    int o4 = (t % 32) * 4;
    float inv = rsqrtf(1.0f + 1e-5f);
    for (int it = 0; it < NITER; it++) {
        __syncthreads();
        int p0 = base + it * 4;
        for (int i = t; i < 4 * 256; i += 128) {
            int pp = i / 256, c = i % 256;
            long pt = p0 + pp;
            rows[pp * 256 + c] = (c < 128) ? H3[pt * 128 + c] : S3[pt * 128 + c - 128];
        }
        __syncthreads();
        unsigned long long acc2[2] = {0ull, 0ull};
        for (int c = 0; c < 256; c++) {
            ulonglong2 wp = *(const ulonglong2*)&wts[c * 128 + o4];
            unsigned long long xd = dup2(rows[pl * 256 + c]);
            ffma2(acc2[0], wp.x, xd);
            ffma2(acc2[1], wp.y, xd);
        }
        float2 axy = unpk2(acc2[0]);
        float2 azw = unpk2(acc2[1]);
        float4 gmv = *(const float4*)&eg[o4];
        float4 btv = *(const float4*)&eb[o4];
        float4 r;
        { float v = gmv.x*inv*axy.x + btv.x; r.x = v>=0.f?v:0.2f*v; }
        { float v = gmv.y*inv*axy.y + btv.y; r.y = v>=0.f?v:0.2f*v; }
        { float v = gmv.z*inv*azw.x + btv.z; r.z = v>=0.f?v:0.2f*v; }
        { float v = gmv.w*inv*azw.y + btv.w; r.w = v>=0.f?v:0.2f*v; }
        long pt = p0 + pl;
        *(float4*)&emb[pt * 128 + o4] = r;
    }
}

// ------------------------------------------------------------------ attention pieces
__global__ void gcfused_kernel(const float* __restrict__ emb, const float* __restrict__ att_w,
                               float* __restrict__ gc) {
    __shared__ float part[8][128];
    __shared__ float es[128];
    int b = blockIdx.x, t = threadIdx.x;      // 1024 threads
    int seg = t >> 7, f = t & 127;
    const float* p = emb + ((long)(b*NPT) + seg*128) * 128 + f;
    float a = 0.f;
    #pragma unroll 4
    for (int n = 0; n < 128; n++) a += p[n * 128];
    part[seg][f] = a;
    __syncthreads();
    if (t < 128) {
        float s = 0.f;
        #pragma unroll
        for (int s8 = 0; s8 < 8; s8++) s += part[s8][t];
        es[t] = s;
    }
    __syncthreads();
    if (t < 128) {
        float gv = 0.f;
        for (int f2 = 0; f2 < 128; f2++) gv += es[f2] * att_w[f2 * 128 + t];
        gc[b * 128 + t] = tanhf(gv * (1.0f / NPT));
    }
}

__global__ void sc_kernel(const float* __restrict__ emb, const float* __restrict__ gc,
                          float* __restrict__ att) {
    int warp = threadIdx.x >> 5, lane = threadIdx.x & 31;
    int pid = blockIdx.x * 4 + warp;
    int b = pid >> 10;
    float a = 0.f;
    #pragma unroll
    for (int j = 0; j < 4; j++) {
        int f = lane + 32 * j;
        a += emb[(long)pid * 128 + f] * gc[b * 128 + f];
    }
    #pragma unroll
    for (int off = 16; off; off >>= 1) a += __shfl_down_sync(0xffffffffu, a, off);
    if (lane == 0) att[pid] = 1.0f / (1.0f + expf(-a));
}

__global__ void pool_part(const float* __restrict__ emb, const float* __restrict__ att,
                          float* __restrict__ part) {
    int b = blockIdx.x, seg = blockIdx.y, f = threadIdx.x;
    const float* p = emb + ((long)(b*NPT) + seg*128) * 128 + f;
    const float* aw = att + b*NPT + seg*128;
    float a = 0.f;
    #pragma unroll 4
    for (int n = 0; n < 128; n++) a += p[n * 128] * aw[n];
    part[(b*8 + seg) * 128 + f] = a;
}

__global__ void pool_fin(const float* __restrict__ part, float* __restrict__ e) {
    int b = blockIdx.x, t = threadIdx.x;
    float a = 0.f;
    #pragma unroll
    for (int s = 0; s < 8; s++) a += part[(b*8 + s) * 128 + t];
    e[b * 128 + t] = a;
}

// ------------------------------------------------------------------ final scoring
__global__ void final_kernel(const float* __restrict__ e, const float* __restrict__ tn_w,
                             const float* __restrict__ tn_wb, const float* __restrict__ tn_bias,
                             const float* __restrict__ fc1_w, const float* __restrict__ fc1_b,
                             const float* __restrict__ sc_w, const float* __restrict__ sc_b,
                             float* __restrict__ out) {
    __shared__ float e1s[128], e2s[128], red[128], ts[16], hs[16];
    int b = blockIdx.x, tid = threadIdx.x;
    e1s[tid] = e[b * 128 + tid];
    e2s[tid] = e[(b + 8) * 128 + tid];
    __syncthreads();
    for (int tt = 0; tt < 16; tt++) {
        float inner = 0.f;
        const float* wrow = tn_w + (long)tid * 128 * 16 + tt;
        for (int gI = 0; gI < 128; gI++) inner += wrow[gI * 16] * e2s[gI];
        red[tid] = e1s[tid] * inner;
        __syncthreads();
        for (int s2 = 64; s2; s2 >>= 1) {
            if (tid < s2) red[tid] += red[tid + s2];
            __syncthreads();
        }
        if (tid == 0) ts[tt] = red[0];
        __syncthreads();
    }
    if (tid < 16) {
        float blk = 0.f;
        for (int c = 0; c < 128; c++) blk += tn_wb[tid * 256 + c] * e1s[c];
        for (int c = 0; c < 128; c++) blk += tn_wb[tid * 256 + 128 + c] * e2s[c];
        float v = ts[tid] + blk + tn_bias[tid];
        ts[tid] = v > 0.f ? v : 0.f;
    }
    __syncthreads();
    if (tid < 16) {
        float h = fc1_b[tid];
        for (int u2 = 0; u2 < 16; u2++) h += fc1_w[tid * 16 + u2] * ts[u2];
        hs[tid] = h > 0.f ? h : 0.f;
    }
    __syncthreads();
    if (tid == 0) {
        float z = sc_b[0];
        for (int u2 = 0; u2 < 16; u2++) z += sc_w[u2] * hs[u2];
        out[b] = 1.0f / (1.0f + expf(-z));
    }
}

// ------------------------------------------------------------------ host
template <typename T>
static float* symaddr(T& sym_) {
    void* p = nullptr;
    cudaGetSymbolAddress(&p, sym_);
    return (float*)p;
}

extern "C" void kernel_launch(void* const* d_in, const int* in_sizes, int n_in,
                              void* d_out, int out_size) {
    (void)in_sizes; (void)n_in; (void)out_size;
    const float* f1    = (const float*)d_in[0];
    const float* f2    = (const float*)d_in[1];
    const float* sw1   = (const float*)d_in[2];
    const float* sg1   = (const float*)d_in[3];
    const float* sb1   = (const float*)d_in[4];
    const float* fw1   = (const float*)d_in[5];
    const float* fg1   = (const float*)d_in[6];
    const float* fb1   = (const float*)d_in[7];
    const float* sw2   = (const float*)d_in[8];
    const float* sg2   = (const float*)d_in[9];
    const float* sb2   = (const float*)d_in[10];
    const float* fw2   = (const float*)d_in[11];
    const float* fg2   = (const float*)d_in[12];
    const float* fb2   = (const float*)d_in[13];
    const float* sw3   = (const float*)d_in[14];
    const float* sg3   = (const float*)d_in[15];
    const float* sb3   = (const float*)d_in[16];
    const float* fw3   = (const float*)d_in[17];
    const float* fg3   = (const float*)d_in[18];
    const float* fb3   = (const float*)d_in[19];
    const float* ew    = (const float*)d_in[20];
    const float* eg    = (const float*)d_in[21];
    const float* ebv   = (const float*)d_in[22];
    const float* att_w = (const float*)d_in[23];
    const float* tn_w  = (const float*)d_in[24];
    const float* tn_wb = (const float*)d_in[25];
    const float* tn_b  = (const float*)d_in[26];
    const float* fc1_w = (const float*)d_in[27];
    const float* fc1_b = (const float*)d_in[28];
    const float* sc_w  = (const float*)d_in[29];
    const float* sc_b  = (const float*)d_in[30];
    float* out = (float*)d_out;

    unsigned* negp = (unsigned*)symaddr(g_neg);
    int*   idxp  = (int*)symaddr(g_idx);
    float* xxp   = symaddr(g_xx);
    float* x0p   = symaddr(g_x0);
    float* s0p   = symaddr(g_s0);
    float* hAp   = symaddr(g_hA);
    float* hBp   = symaddr(g_hB);
    float* h3p   = symaddr(g_h3);
    float* embp  = symaddr(g_emb);
    float* partp = symaddr(g_part);
    float* gcp   = symaddr(g_gc);
    float* ep    = symaddr(g_e);

    // conv smem sizes: 2*COUT*(CROW+2) weights + P*21*(CPH+4) nb (floats) + P*KNN idx
    const int SM_C1 = (2*64*6    + 8*21*8 ) * 4 + 8*KNN*4;    // conv<3,4,64,8,256,1>
    const int SM_C2 = (2*64*66   + 8*21*68) * 4 + 8*KNN*4;    // conv<64,64,64,8,256,1>
    const int SM_C3 = (2*128*66  + 8*21*68) * 4 + 8*KNN*4;    // conv<64,64,128,8,512,1>
    const int SM_C4 = (2*64*130  + 16*21*68) * 4 + 16*KNN*4;  // conv<128,128,64,16,512,2>
    const int SM_EW = (256*128 + 4*256) * 4;

    cudaFuncSetAttribute(conv_kernel<64,64,64,8,256,1>,    cudaFuncAttributeMaxDynamicSharedMemorySize, SM_C2);
    cudaFuncSetAttribute(conv_kernel<64,64,128,8,512,1>,   cudaFuncAttributeMaxDynamicSharedMemorySize, SM_C3);
    cudaFuncSetAttribute(conv_kernel<128,128,64,16,512,2>, cudaFuncAttributeMaxDynamicSharedMemorySize, SM_C4);
    cudaFuncSetAttribute(emb_kernel,                       cudaFuncAttributeMaxDynamicSharedMemorySize, SM_EW);

    // streams/events for layer-1 fork (created once; resource init only, work is identical every call)
    static cudaStream_t sB = 0;
    static cudaEvent_t evFork = 0, evJoin = 0;
    if (!sB) {
        cudaStreamCreateWithFlags(&sB, cudaStreamNonBlocking);
        cudaEventCreateWithFlags(&evFork, cudaEventDisableTiming);
        cudaEventCreateWithFlags(&evJoin, cudaEventDisableTiming);
    }

    transpose_kernel<<<(NB*131*NPT + 255) / 256, 256>>>(f1, f2, x0p, s0p);
    cudaEventRecord(evFork, 0);
    cudaStreamWaitEvent(sB, evFork, 0);

    // ---- layer 1: xyz chain on stream 0, sem chain on stream sB (parallel) ----
    xx_kernel<4,NROW><<<NROW/256, 256>>>(x0p, xxp);
    dist_kernel<4><<<dim3(8,8,NB), 256>>>(x0p, xxp, negp);
    topk_kernel<<<NROW/8, 256>>>(negp, idxp);
    conv_kernel<3,4,64,8,256,1><<<NB*NPT/8, 256, SM_C1>>>(x0p, idxp, sw1, sw1, sg1, sg1, sb1, sb1, hAp);

    xx_kernel<128,NROW><<<NROW/256, 256, 0, sB>>>(s0p, xxp + NROW);
    dist_kernel<128><<<dim3(8,8,NB), 256, 0, sB>>>(s0p, xxp + NROW, negp + (size_t)NROW*NPT);
    topk_kernel<<<NROW/8, 256, 0, sB>>>(negp + (size_t)NROW*NPT, idxp + NROW*KNN);
    conv_kernel<128,128,64,16,512,2><<<NB*NPT/16, 512, SM_C4, sB>>>(s0p, idxp + NROW*KNN, fw1, fw1, fg1, fg1, fb1, fb1, hAp + NROW*64);

    cudaEventRecord(evJoin, sB);
    cudaStreamWaitEvent(0, evJoin, 0);

    // ---- layer 2 (both chains merged, 64 -> 64) ----
    xx_kernel<64,NROW2><<<NROW2/256, 256>>>(hAp, xxp);
    dist_kernel<64><<<dim3(8,8,NB2), 256>>>(hAp, xxp, negp);
    topk_kernel<<<NROW2/8, 256>>>(negp, idxp);
    conv_kernel<64,64,64,8,256,1><<<NB2*NPT/8, 256, SM_C2>>>(hAp, idxp, sw2, fw2, sg2, fg2, sb2, fb2, hBp);

    // ---- layer 3 (both chains merged, 64 -> 128) ----
    xx_kernel<64,NROW2><<<NROW2/256, 256>>>(hBp, xxp);
    dist_kernel<64><<<dim3(8,8,NB2), 256>>>(hBp, xxp, negp);
    topk_kernel<<<NROW2/8, 256>>>(negp, idxp);
    conv_kernel<64,64,128,8,512,1><<<NB2*NPT/8, 512, SM_C3>>>(hBp, idxp, sw3, fw3, sg3, fg3, sb3, fb3, h3p);

    // ---- fuse + attention (all 16 batches) ----
    emb_kernel<<<NROW/32, 128, SM_EW>>>(h3p, h3p + NROW*128, ew, eg, ebv, embp);

    float* att_out = out + 8;                       // att1 (b 0..7) then att2 (b 8..15), contiguous
    gcfused_kernel<<<NB, 1024>>>(embp, att_w, gcp);
    sc_kernel<<<NROW/4, 128>>>(embp, gcp, att_out);
    pool_part<<<dim3(NB, 8), 128>>>(embp, att_out, partp);
    pool_fin<<<NB, 128>>>(partp, ep);

    final_kernel<<<BB, 128>>>(ep, tn_w, tn_wb, tn_b, fc1_w, fc1_b, sc_w, sc_b, out);
}